// round 3
// baseline (speedup 1.0000x reference)
#include <cuda_runtime.h>
#include <math.h>

#define Bn   256
#define Tn   512
#define NT   (Bn*Tn)          // 131072 tokens
#define HID  256
#define WPAD 33
#define GRU_SMEM ((3*256*WPAD + 256*WPAD)*4)   // 135168 bytes

// ----------------- device scratch (bss-zeroed at module load) -----------------
__device__ float g_xw  [(size_t)NT*1536];   // input-gate precompute, reused per layer
__device__ float g_bufA[(size_t)NT*512];    // activations ping (layer0 packed [NT][128])
__device__ float g_bufB[(size_t)NT*512];    // activations pong
__device__ float g_h   [2*2*256*256];       // h ping-pong: [pp][dir][sample(perm)][256]
__device__ unsigned int g_bar[16];          // per-(dir,btile) barrier counters
__device__ int   g_perm[256];               // batch order sorted by length desc

// ----------------- packed f32x2 helpers (Blackwell FFMA2) -----------------
__device__ __forceinline__ unsigned long long pk2(float lo, float hi) {
    unsigned long long r;
    asm("mov.b64 %0, {%1, %2};" : "=l"(r) : "f"(lo), "f"(hi));
    return r;
}
__device__ __forceinline__ void fma2(unsigned long long &d, unsigned long long a, unsigned long long b) {
    asm("fma.rn.f32x2 %0, %1, %2, %0;" : "+l"(d) : "l"(a), "l"(b));
}
__device__ __forceinline__ float2 upk2(unsigned long long v) {
    float2 f;
    asm("mov.b64 {%0, %1}, %2;" : "=f"(f.x), "=f"(f.y) : "l"(v));
    return f;
}

// ----------------- sort batch indices by length descending -----------------
__global__ void halt_sort_perm(const int* __restrict__ lengths) {
    __shared__ int key[256];
    __shared__ int idx[256];
    int tid = threadIdx.x;
    key[tid] = -lengths[tid];   // ascending by -len == descending by len
    idx[tid] = tid;
    __syncthreads();
    for (int k = 2; k <= 256; k <<= 1)
        for (int j = k >> 1; j > 0; j >>= 1) {
            int ixj = tid ^ j;
            if (ixj > tid) {
                bool asc = ((tid & k) == 0);
                int a = key[tid], c = key[ixj];
                bool gt = a > c;
                if (asc == gt) {
                    key[tid] = c; key[ixj] = a;
                    int t2 = idx[tid]; idx[tid] = idx[ixj]; idx[ixj] = t2;
                }
            }
            __syncthreads();
        }
    g_perm[tid] = idx[tid];
}

// ----------------- input projection: LN -> Linear(25->128) -> GELU -> Linear(128->128) -----------------
__global__ void halt_proj(const float* __restrict__ x, const int* __restrict__ lengths,
                          const float* __restrict__ ln_g, const float* __restrict__ ln_b,
                          const float* __restrict__ w1, const float* __restrict__ b1,
                          const float* __restrict__ w2, const float* __restrict__ b2) {
    int token = blockIdx.x;
    int b = token >> 9, t = token & 511;
    if (t >= lengths[b]) return;     // padded rows stay 0 (bss), never read downstream
    __shared__ float sx[25], sn[25], sh1[128];
    int tid = threadIdx.x;
    if (tid < 25) sx[tid] = x[(size_t)token*25 + tid];
    __syncthreads();
    float mu = 0.f;
#pragma unroll
    for (int i = 0; i < 25; i++) mu += sx[i];
    mu *= (1.0f/25.0f);
    float var = 0.f;
#pragma unroll
    for (int i = 0; i < 25; i++) { float d = sx[i]-mu; var += d*d; }
    var *= (1.0f/25.0f);
    float rstd = rsqrtf(var + 1e-5f);
    if (tid < 25) sn[tid] = (sx[tid]-mu)*rstd*ln_g[tid] + ln_b[tid];
    __syncthreads();
    float a = b1[tid];
#pragma unroll
    for (int i = 0; i < 25; i++) a += sn[i]*w1[i*128 + tid];
    float ge = 0.5f*a*(1.0f + erff(a*0.70710678118654752440f));  // exact GELU
    sh1[tid] = ge;
    __syncthreads();
    float o = b2[tid];
#pragma unroll 8
    for (int i = 0; i < 128; i++) o += sh1[i]*w2[i*128 + tid];
    g_bufA[(size_t)token*128 + tid] = o;
}

// ----------------- xw GEMM: C[NT,1536] = A[NT,K] * W[1536,K]^T + bias -----------------
__global__ __launch_bounds__(256)
void halt_sgemm(const float* __restrict__ A, int K,
                const float* __restrict__ W, const float* __restrict__ bias,
                float* __restrict__ C, const int* __restrict__ lengths) {
    int m0 = blockIdx.x * 128;
    int n0 = blockIdx.y * 128;
    int b = m0 >> 9;
    if ((m0 & 511) >= lengths[b]) return;   // fully-padded tile: outputs never read
    __shared__ float As[8][128];
    __shared__ float Bs[8][128];
    int tid = threadIdx.x;
    int lrow = tid >> 1, lk = (tid & 1) * 4;
    int tx = tid & 15, ty = tid >> 4;
    const float* Ap = A + (size_t)(m0 + lrow)*K + lk;
    const float* Wp = W + (size_t)(n0 + lrow)*K + lk;
    unsigned long long acc[8][4];
#pragma unroll
    for (int i = 0; i < 8; i++)
#pragma unroll
        for (int jp = 0; jp < 4; jp++) acc[i][jp] = 0ull;

    for (int k0 = 0; k0 < K; k0 += 8) {
        float4 av = *(const float4*)(Ap + k0);
        float4 wv = *(const float4*)(Wp + k0);
        __syncthreads();
        As[lk+0][lrow] = av.x; As[lk+1][lrow] = av.y;
        As[lk+2][lrow] = av.z; As[lk+3][lrow] = av.w;
        Bs[lk+0][lrow] = wv.x; Bs[lk+1][lrow] = wv.y;
        Bs[lk+2][lrow] = wv.z; Bs[lk+3][lrow] = wv.w;
        __syncthreads();
#pragma unroll
        for (int ks = 0; ks < 8; ks++) {
            unsigned long long bp[4];
#pragma unroll
            for (int jp = 0; jp < 4; jp++)
                bp[jp] = *(const unsigned long long*)&Bs[ks][tx*8 + jp*2];
#pragma unroll
            for (int i = 0; i < 8; i++) {
                float a = As[ks][ty*8 + i];
                unsigned long long ap = pk2(a, a);
#pragma unroll
                for (int jp = 0; jp < 4; jp++) fma2(acc[i][jp], ap, bp[jp]);
            }
        }
    }
#pragma unroll
    for (int i = 0; i < 8; i++) {
        size_t row = (size_t)(m0 + ty*8 + i)*1536 + n0 + tx*8;
#pragma unroll
        for (int jp = 0; jp < 4; jp++) {
            float2 v = upk2(acc[i][jp]);
            int col = n0 + tx*8 + jp*2;
            v.x += bias[col]; v.y += bias[col+1];
            *(float2*)&C[row + jp*2] = v;
        }
    }
}

// ----------------- persistent GRU layer (both dirs), per-(dir,btile) barriers -----------------
__global__ __launch_bounds__(128)
void halt_gru(const float* __restrict__ xw, float* __restrict__ y,
              const float* __restrict__ Whh, const float* __restrict__ bhh,
              const int* __restrict__ lengths) {
    extern __shared__ float sm[];
    float* Wsm = sm;                      // [3][256][WPAD]: Wsm[g][k][j]
    float* hsm = sm + 3*256*WPAD;         // [256][WPAD]:    hsm[k][s]
    int bid = blockIdx.x;
    int dir = bid >> 6;
    int hc  = (bid >> 3) & 7;
    int bt  = bid & 7;
    int jg0 = hc * 32;
    int tid = threadIdx.x;
    int j = tid & 31, sg = tid >> 5, s0 = sg * 8;

    // preload Whh slice (coalesced over k; smem stride WPAD=33 -> conflict-free)
    const float* Wd = Whh + (size_t)dir*768*256;
    for (int it = tid; it < 3*32*256; it += 128) {
        int k = it & 255, gj = it >> 8, jj = gj & 31, g = gj >> 5;
        Wsm[g*(256*WPAD) + k*WPAD + jj] = Wd[(size_t)(g*256 + jg0 + jj)*256 + k];
    }
    float bh_r = bhh[dir*768 +        jg0 + j];
    float bh_z = bhh[dir*768 + 256 +  jg0 + j];
    float bh_n = bhh[dir*768 + 512 +  jg0 + j];
    int pb[8], lenv[8];
#pragma unroll
    for (int i = 0; i < 8; i++) {
        pb[i]   = g_perm[bt*32 + s0 + i];
        lenv[i] = lengths[pb[i]];
    }
    int tmax = lengths[g_perm[bt*32]];   // max length in this tile (sorted desc)
    int grp = dir*8 + bt;
    __syncthreads();

    for (int t = 0; t < tmax; t++) {
        // load full h[32 samples][256] from global ping buffer (L2, bypass L1)
        const float* hin = g_h + ((size_t)((t & 1)*2 + dir)*256 + bt*32)*256;
        for (int it = tid; it < 32*256; it += 128) {
            int s = it >> 8, k = it & 255;
            hsm[k*WPAD + s] = __ldcg(&hin[s*256 + k]);
        }
        __syncthreads();

        // gh = Whh_slice @ h  (3 gates x 1 j x 8 samples per thread, f32x2 packed)
        unsigned long long ar[4] = {0,0,0,0}, az[4] = {0,0,0,0}, an[4] = {0,0,0,0};
        const float* Wr = Wsm + j;
        const float* Wz = Wsm + 256*WPAD + j;
        const float* Wn = Wsm + 2*256*WPAD + j;
        const float* hb = hsm + s0;
#pragma unroll 4
        for (int k = 0; k < 256; k++) {
            float wr = Wr[k*WPAD], wz = Wz[k*WPAD], wn = Wn[k*WPAD];
            unsigned long long pr = pk2(wr, wr), pz = pk2(wz, wz), pn = pk2(wn, wn);
#pragma unroll
            for (int i = 0; i < 4; i++) {
                unsigned long long hp = pk2(hb[k*WPAD + 2*i], hb[k*WPAD + 2*i + 1]);
                fma2(ar[i], pr, hp); fma2(az[i], pz, hp); fma2(an[i], pn, hp);
            }
        }

        // pointwise gate update + state/output writes
        float* hout = g_h + ((size_t)(((t+1) & 1)*2 + dir)*256 + bt*32)*256;
#pragma unroll
        for (int i = 0; i < 4; i++) {
            float2 rr = upk2(ar[i]), zz = upk2(az[i]), nn = upk2(an[i]);
#pragma unroll
            for (int u = 0; u < 2; u++) {
                int si = 2*i + u;
                if (t < lenv[si]) {
                    float gr = (u ? rr.y : rr.x) + bh_r;
                    float gz = (u ? zz.y : zz.x) + bh_z;
                    float gn = (u ? nn.y : nn.x) + bh_n;
                    int tok = dir ? (lenv[si] - 1 - t) : t;
                    size_t base = (size_t)pb[si]*512 + tok;
                    const float* xp = xw + base*1536 + dir*768 + jg0 + j;
                    float r = 1.f/(1.f + expf(-(xp[0]   + gr)));
                    float z = 1.f/(1.f + expf(-(xp[256] + gz)));
                    float n = tanhf(xp[512] + r*gn);
                    float hold = hsm[(jg0 + j)*WPAD + s0 + si];
                    float hnew = (1.f - z)*n + z*hold;
                    y[base*512 + dir*256 + jg0 + j] = hnew;
                    hout[(s0 + si)*256 + jg0 + j] = hnew;
                }
            }
        }
        __threadfence();
        __syncthreads();
        if (tid == 0) {
            atomicAdd(&g_bar[grp], 1u);
            unsigned int tgt = (unsigned int)(t + 1) * 8u;
            while (atomicAdd(&g_bar[grp], 0u) < tgt) __nanosleep(64);
        }
        __syncthreads();
    }
}

// ----------------- top-k pooling + classifier -----------------
__global__ __launch_bounds__(256)
void halt_pool(const float* __restrict__ H, const int* __restrict__ lengths,
               const float* __restrict__ Wc, const float* __restrict__ bc,
               float* __restrict__ out) {
    int b = blockIdx.x, tid = threadIdx.x;
    __shared__ float ns[512];
    __shared__ int   si[512];
    __shared__ float red[256];
    int len = lengths[b];
    for (int t = tid; t < 512; t += 256) {
        float sc = 1e9f;                         // sentinel (negscore): sorts last
        if (t < len) {
            const float* row = H + ((size_t)b*512 + t)*512;
            float acc = 0.f;
#pragma unroll 8
            for (int d = 0; d < 512; d++) { float v = row[d]; acc += v*v; }
            sc = -sqrtf(acc);                    // ascending by -score == descending score
        }
        ns[t] = sc; si[t] = t;
    }
    __syncthreads();
    for (int k = 2; k <= 512; k <<= 1)
        for (int j = k >> 1; j > 0; j >>= 1) {
            for (int i = tid; i < 512; i += 256) {
                int ixj = i ^ j;
                if (ixj > i) {
                    bool asc = ((i & k) == 0);
                    float a = ns[i], c = ns[ixj];
                    int ia = si[i], ic = si[ixj];
                    bool gt = (a > c) || (a == c && ia > ic);   // tie: idx ascending (stable)
                    if (asc == gt) { ns[i] = c; ns[ixj] = a; si[i] = ic; si[ixj] = ia; }
                }
            }
            __syncthreads();
        }
    int kk = (int)ceilf((float)len * 0.15f);   // replicate f32 rounding of reference exactly
    if (kk < 1) kk = 1;
    float a0 = 0.f, a1 = 0.f;
    for (int i = 0; i < kk; i++) {
        int r = si[i];
        const float* row = H + ((size_t)b*512 + r)*512;
        a0 += row[tid]; a1 += row[tid + 256];
    }
    float kf = (float)kk;
    float part = (a0/kf)*Wc[tid] + (a1/kf)*Wc[tid + 256];
    red[tid] = part;
    __syncthreads();
    for (int s2 = 128; s2 > 0; s2 >>= 1) {
        if (tid < s2) red[tid] += red[tid + s2];
        __syncthreads();
    }
    if (tid == 0) out[b] = red[0] + bc[0];
}

// ----------------- host orchestration -----------------
extern "C" void kernel_launch(void* const* d_in, const int* in_sizes, int n_in,
                              void* d_out, int out_size) {
    const float* x    = (const float*)d_in[0];
    const int*   lens = (const int*)  d_in[1];
    const float* ln_g = (const float*)d_in[2];
    const float* ln_b = (const float*)d_in[3];
    const float* w1   = (const float*)d_in[4];
    const float* b1   = (const float*)d_in[5];
    const float* w2   = (const float*)d_in[6];
    const float* b2   = (const float*)d_in[7];
    const float* Wih0 = (const float*)d_in[8];
    const float* Whh0 = (const float*)d_in[9];
    const float* bih0 = (const float*)d_in[10];
    const float* bhh0 = (const float*)d_in[11];
    const float* Wih  = (const float*)d_in[12];
    const float* Whh  = (const float*)d_in[13];
    const float* bih  = (const float*)d_in[14];
    const float* bhh  = (const float*)d_in[15];
    const float* Wc   = (const float*)d_in[16];
    const float* bc   = (const float*)d_in[17];
    float* out = (float*)d_out;

    cudaFuncSetAttribute(halt_gru, cudaFuncAttributeMaxDynamicSharedMemorySize, GRU_SMEM);

    void *barp = 0, *hp = 0, *pA = 0, *pB = 0, *pxw = 0;
    cudaGetSymbolAddress(&barp, g_bar);
    cudaGetSymbolAddress(&hp,   g_h);
    cudaGetSymbolAddress(&pA,   g_bufA);
    cudaGetSymbolAddress(&pB,   g_bufB);
    cudaGetSymbolAddress(&pxw,  g_xw);
    float* fA  = (float*)pA;
    float* fB  = (float*)pB;
    float* fxw = (float*)pxw;

    halt_sort_perm<<<1, 256>>>(lens);
    halt_proj<<<NT, 128>>>(x, lens, ln_g, ln_b, w1, b1, w2, b2);

    dim3 gg(NT/128, 12);
    for (int l = 0; l < 5; l++) {
        const float* Wi = l ? (Wih + (size_t)(l-1)*2*768*512) : Wih0;
        const float* bi = l ? (bih + (l-1)*1536) : bih0;
        const float* Wh = l ? (Whh + (size_t)(l-1)*2*768*256) : Whh0;
        const float* bh = l ? (bhh + (l-1)*1536) : bhh0;
        int K = l ? 512 : 128;
        float* Ain  = (l & 1) ? fB : fA;
        float* Yout = (l & 1) ? fA : fB;
        cudaMemsetAsync(barp, 0, 16*sizeof(unsigned int));
        cudaMemsetAsync(hp,   0, (size_t)2*2*256*256*sizeof(float));
        halt_sgemm<<<gg, 256>>>(Ain, K, Wi, bi, fxw, lens);
        halt_gru<<<128, 128, GRU_SMEM>>>(fxw, Yout, Wh, bh, lens);
    }
    halt_pool<<<256, 256>>>(fB, lens, Wc, bc, out);
}

// round 5
// speedup vs baseline: 1.6246x; 1.6246x over previous
#include <cuda_runtime.h>
#include <math.h>

#define Bn   256
#define Tn   512
#define NT   (Bn*Tn)          // 131072 tokens

// GRU smem: Wsm [3][16][258] + hsm [32][260]
#define WSM_FLOATS (3*16*258)            // 12384
#define HSM_FLOATS (32*260)              // 8320
#define GRU_SMEM   ((WSM_FLOATS + HSM_FLOATS)*4)   // 82816 bytes

// ----------------- device scratch (bss-zeroed at module load) -----------------
__device__ float g_xw  [(size_t)NT*1536];   // input-gate precompute, reused per layer
__device__ float g_bufA[(size_t)NT*512];    // activations ping (layer0 packed [NT][128])
__device__ float g_bufB[(size_t)NT*512];    // activations pong
__device__ float g_h   [2*2*256*256];       // h ping-pong: [pp][dir][sample(perm)][256]
__device__ unsigned int g_bar[16];          // per-(dir,btile) barrier counters
__device__ int   g_perm[256];               // batch order sorted by length desc

// ----------------- packed f32x2 helpers (Blackwell FFMA2) -----------------
__device__ __forceinline__ unsigned long long pk2(float lo, float hi) {
    unsigned long long r;
    asm("mov.b64 %0, {%1, %2};" : "=l"(r) : "f"(lo), "f"(hi));
    return r;
}
__device__ __forceinline__ void fma2(unsigned long long &d, unsigned long long a, unsigned long long b) {
    asm("fma.rn.f32x2 %0, %1, %2, %0;" : "+l"(d) : "l"(a), "l"(b));
}
__device__ __forceinline__ float2 upk2(unsigned long long v) {
    float2 f;
    asm("mov.b64 {%0, %1}, %2;" : "=f"(f.x), "=f"(f.y) : "l"(v));
    return f;
}

// ----------------- sort batch indices by length descending -----------------
__global__ void halt_sort_perm(const int* __restrict__ lengths) {
    __shared__ int key[256];
    __shared__ int idx[256];
    int tid = threadIdx.x;
    key[tid] = -lengths[tid];
    idx[tid] = tid;
    __syncthreads();
    for (int k = 2; k <= 256; k <<= 1)
        for (int j = k >> 1; j > 0; j >>= 1) {
            int ixj = tid ^ j;
            if (ixj > tid) {
                bool asc = ((tid & k) == 0);
                int a = key[tid], c = key[ixj];
                bool gt = a > c;
                if (asc == gt) {
                    key[tid] = c; key[ixj] = a;
                    int t2 = idx[tid]; idx[tid] = idx[ixj]; idx[ixj] = t2;
                }
            }
            __syncthreads();
        }
    g_perm[tid] = idx[tid];
}

// ----------------- input projection: LN -> Linear(25->128) -> GELU -> Linear(128->128) -----------------
__global__ void halt_proj(const float* __restrict__ x, const int* __restrict__ lengths,
                          const float* __restrict__ ln_g, const float* __restrict__ ln_b,
                          const float* __restrict__ w1, const float* __restrict__ b1,
                          const float* __restrict__ w2, const float* __restrict__ b2) {
    int token = blockIdx.x;
    int b = token >> 9, t = token & 511;
    if (t >= lengths[b]) return;
    __shared__ float sx[25], sn[25], sh1[128];
    int tid = threadIdx.x;
    if (tid < 25) sx[tid] = x[(size_t)token*25 + tid];
    __syncthreads();
    float mu = 0.f;
#pragma unroll
    for (int i = 0; i < 25; i++) mu += sx[i];
    mu *= (1.0f/25.0f);
    float var = 0.f;
#pragma unroll
    for (int i = 0; i < 25; i++) { float d = sx[i]-mu; var += d*d; }
    var *= (1.0f/25.0f);
    float rstd = rsqrtf(var + 1e-5f);
    if (tid < 25) sn[tid] = (sx[tid]-mu)*rstd*ln_g[tid] + ln_b[tid];
    __syncthreads();
    float a = b1[tid];
#pragma unroll
    for (int i = 0; i < 25; i++) a += sn[i]*w1[i*128 + tid];
    float ge = 0.5f*a*(1.0f + erff(a*0.70710678118654752440f));
    sh1[tid] = ge;
    __syncthreads();
    float o = b2[tid];
#pragma unroll 8
    for (int i = 0; i < 128; i++) o += sh1[i]*__ldg(&w2[i*128 + tid]);
    g_bufA[(size_t)token*128 + tid] = o;
}

// ----------------- xw GEMM: C[NT,1536] = A[NT,K] * W[1536,K]^T + bias -----------------
// 128x128 tile, BK=16, double-buffered, warp tile 32x64, thread 8x8, f32x2 packed.
__global__ __launch_bounds__(256)
void halt_sgemm(const float* __restrict__ A, int K,
                const float* __restrict__ W, const float* __restrict__ bias,
                float* __restrict__ C, const int* __restrict__ lengths) {
    int m0 = blockIdx.x * 128;
    int n0 = blockIdx.y * 128;
    if ((m0 & 511) >= lengths[m0 >> 9]) return;   // fully-padded tile: outputs never read
    __shared__ float As[2][16][128];
    __shared__ float Bs[2][16][128];
    int tid  = threadIdx.x;
    int lrow = tid & 127, kh = tid >> 7;          // loader: row + k-half
    int warp = tid >> 5, lane = tid & 31;
    int wm = warp & 3, wn = warp >> 2;            // 4 x 2 warps
    int lm = lane & 3, ln = lane >> 2;            // 4 x 8 lanes
    int tm = wm*32 + lm*8, tn = wn*64 + ln*8;

    const float* Ap = A + (size_t)(m0 + lrow)*K + kh*8;
    const float* Wp = W + (size_t)(n0 + lrow)*K + kh*8;

    unsigned long long acc[8][4];
#pragma unroll
    for (int i = 0; i < 8; i++)
#pragma unroll
        for (int jp = 0; jp < 4; jp++) acc[i][jp] = 0ull;

    // prologue: stage 0
    {
        float4 a0 = *(const float4*)(Ap + 0);
        float4 a1 = *(const float4*)(Ap + 4);
        float4 w0 = *(const float4*)(Wp + 0);
        float4 w1v= *(const float4*)(Wp + 4);
        int kb = kh*8;
        As[0][kb+0][lrow]=a0.x; As[0][kb+1][lrow]=a0.y; As[0][kb+2][lrow]=a0.z; As[0][kb+3][lrow]=a0.w;
        As[0][kb+4][lrow]=a1.x; As[0][kb+5][lrow]=a1.y; As[0][kb+6][lrow]=a1.z; As[0][kb+7][lrow]=a1.w;
        Bs[0][kb+0][lrow]=w0.x; Bs[0][kb+1][lrow]=w0.y; Bs[0][kb+2][lrow]=w0.z; Bs[0][kb+3][lrow]=w0.w;
        Bs[0][kb+4][lrow]=w1v.x;Bs[0][kb+5][lrow]=w1v.y;Bs[0][kb+6][lrow]=w1v.z;Bs[0][kb+7][lrow]=w1v.w;
    }
    __syncthreads();

    int buf = 0;
    for (int k0 = 16; k0 < K; k0 += 16) {
        float4 a0 = *(const float4*)(Ap + k0);
        float4 a1 = *(const float4*)(Ap + k0 + 4);
        float4 w0 = *(const float4*)(Wp + k0);
        float4 w1v= *(const float4*)(Wp + k0 + 4);
#pragma unroll
        for (int ks = 0; ks < 16; ks++) {
            float4 av0 = *(const float4*)&As[buf][ks][tm];
            float4 av1 = *(const float4*)&As[buf][ks][tm+4];
            float4 bv0 = *(const float4*)&Bs[buf][ks][tn];
            float4 bv1 = *(const float4*)&Bs[buf][ks][tn+4];
            unsigned long long bp[4] = { pk2(bv0.x,bv0.y), pk2(bv0.z,bv0.w),
                                         pk2(bv1.x,bv1.y), pk2(bv1.z,bv1.w) };
            float am[8] = {av0.x,av0.y,av0.z,av0.w,av1.x,av1.y,av1.z,av1.w};
#pragma unroll
            for (int i = 0; i < 8; i++) {
                unsigned long long ap = pk2(am[i], am[i]);
#pragma unroll
                for (int jp = 0; jp < 4; jp++) fma2(acc[i][jp], ap, bp[jp]);
            }
        }
        int nb = buf ^ 1, kb = kh*8;
        As[nb][kb+0][lrow]=a0.x; As[nb][kb+1][lrow]=a0.y; As[nb][kb+2][lrow]=a0.z; As[nb][kb+3][lrow]=a0.w;
        As[nb][kb+4][lrow]=a1.x; As[nb][kb+5][lrow]=a1.y; As[nb][kb+6][lrow]=a1.z; As[nb][kb+7][lrow]=a1.w;
        Bs[nb][kb+0][lrow]=w0.x; Bs[nb][kb+1][lrow]=w0.y; Bs[nb][kb+2][lrow]=w0.z; Bs[nb][kb+3][lrow]=w0.w;
        Bs[nb][kb+4][lrow]=w1v.x;Bs[nb][kb+5][lrow]=w1v.y;Bs[nb][kb+6][lrow]=w1v.z;Bs[nb][kb+7][lrow]=w1v.w;
        __syncthreads();
        buf = nb;
    }
    // last stage
#pragma unroll
    for (int ks = 0; ks < 16; ks++) {
        float4 av0 = *(const float4*)&As[buf][ks][tm];
        float4 av1 = *(const float4*)&As[buf][ks][tm+4];
        float4 bv0 = *(const float4*)&Bs[buf][ks][tn];
        float4 bv1 = *(const float4*)&Bs[buf][ks][tn+4];
        unsigned long long bp[4] = { pk2(bv0.x,bv0.y), pk2(bv0.z,bv0.w),
                                     pk2(bv1.x,bv1.y), pk2(bv1.z,bv1.w) };
        float am[8] = {av0.x,av0.y,av0.z,av0.w,av1.x,av1.y,av1.z,av1.w};
#pragma unroll
        for (int i = 0; i < 8; i++) {
            unsigned long long ap = pk2(am[i], am[i]);
#pragma unroll
            for (int jp = 0; jp < 4; jp++) fma2(acc[i][jp], ap, bp[jp]);
        }
    }

    // epilogue with bias, vectorized stores
    float b0 = bias[n0+tn+0], b1 = bias[n0+tn+1], b2 = bias[n0+tn+2], b3 = bias[n0+tn+3];
    float b4 = bias[n0+tn+4], b5 = bias[n0+tn+5], b6 = bias[n0+tn+6], b7 = bias[n0+tn+7];
#pragma unroll
    for (int i = 0; i < 8; i++) {
        float* cp = C + (size_t)(m0 + tm + i)*1536 + n0 + tn;
        float2 v0 = upk2(acc[i][0]), v1 = upk2(acc[i][1]);
        float2 v2 = upk2(acc[i][2]), v3 = upk2(acc[i][3]);
        float4 o0 = { v0.x+b0, v0.y+b1, v1.x+b2, v1.y+b3 };
        float4 o1 = { v2.x+b4, v2.y+b5, v3.x+b6, v3.y+b7 };
        *(float4*)cp       = o0;
        *(float4*)(cp + 4) = o1;
    }
}

// ----------------- persistent GRU layer: 256 blocks = dir(2) x hc(16) x bt(8) -----------------
// Block: 128 threads = 16 j x 8 sample-groups of 4; FMA packed over k (even/odd halves).
__global__ __launch_bounds__(128)
void halt_gru(const float* __restrict__ xw, float* __restrict__ y,
              const float* __restrict__ Whh, const float* __restrict__ bhh,
              const int* __restrict__ lengths) {
    extern __shared__ float sm[];
    float* Wsm = sm;               // [3][16][258]: Wsm[(g*16+jj)*258 + k]
    float* hsm = sm + WSM_FLOATS;  // [32][260]:    hsm[s*260 + k]
    int bid = blockIdx.x;
    int dir = bid >> 7;
    int hc  = (bid >> 3) & 15;
    int bt  = bid & 7;
    int jg0 = hc * 16;
    int tid = threadIdx.x;
    int j = tid & 15, sg = tid >> 4, s0 = sg * 4;

    // preload Whh slice transposed to [g][j][k] (coalesced over k)
    const float* Wd = Whh + (size_t)dir*768*256;
    for (int it = tid; it < 3*16*256; it += 128) {
        int k = it & 255, jj = (it >> 8) & 15, g = it >> 12;
        Wsm[(g*16 + jj)*258 + k] = Wd[(size_t)(g*256 + jg0 + jj)*256 + k];
    }
    float bh_r = bhh[dir*768 +       jg0 + j];
    float bh_z = bhh[dir*768 + 256 + jg0 + j];
    float bh_n = bhh[dir*768 + 512 + jg0 + j];
    int pb[4], lenv[4];
#pragma unroll
    for (int i = 0; i < 4; i++) {
        pb[i]   = g_perm[bt*32 + s0 + i];
        lenv[i] = lengths[pb[i]];
    }
    int tmax = lengths[g_perm[bt*32]];   // sorted desc -> first is tile max
    int grp = dir*8 + bt;
    unsigned int* barp = &g_bar[grp];
    __syncthreads();

    const float* Wr = Wsm + j*258;
    const float* Wz = Wsm + 16*258 + j*258;
    const float* Wn = Wsm + 32*258 + j*258;

    for (int t = 0; t < tmax; t++) {
        // reload h tile [32][256] from global ping (L2 only), vectorized
        const float* hin = g_h + ((size_t)((t & 1)*2 + dir)*256 + bt*32)*256;
        for (int it = tid; it < 2048; it += 128) {
            int s = it >> 6, f = (it & 63)*4;
            float4 v = __ldcg((const float4*)&hin[s*256 + f]);
            *(float4*)&hsm[s*260 + f] = v;
        }
        __syncthreads();

        // gh = Whh_slice @ h: packed over k (lo=even k, hi=odd k)
        unsigned long long ar[4] = {0,0,0,0}, az[4] = {0,0,0,0}, an[4] = {0,0,0,0};
#pragma unroll 4
        for (int kp = 0; kp < 128; kp++) {
            int k2 = kp*2;
            unsigned long long wr = *(const unsigned long long*)&Wr[k2];
            unsigned long long wz = *(const unsigned long long*)&Wz[k2];
            unsigned long long wn = *(const unsigned long long*)&Wn[k2];
#pragma unroll
            for (int i = 0; i < 4; i++) {
                unsigned long long hp = *(const unsigned long long*)&hsm[(s0+i)*260 + k2];
                fma2(ar[i], wr, hp); fma2(az[i], wz, hp); fma2(an[i], wn, hp);
            }
        }

        float* hout = g_h + ((size_t)(((t+1) & 1)*2 + dir)*256 + bt*32)*256;
#pragma unroll
        for (int i = 0; i < 4; i++) {
            if (t < lenv[i]) {
                float2 rr = upk2(ar[i]), zz = upk2(az[i]), nn = upk2(an[i]);
                float gr = rr.x + rr.y + bh_r;
                float gz = zz.x + zz.y + bh_z;
                float gn = nn.x + nn.y + bh_n;
                int tok = dir ? (lenv[i] - 1 - t) : t;
                size_t base = (size_t)pb[i]*512 + tok;
                const float* xp = xw + base*1536 + dir*768 + jg0 + j;
                float r = 1.f/(1.f + expf(-(xp[0]   + gr)));
                float z = 1.f/(1.f + expf(-(xp[256] + gz)));
                float n = tanhf(xp[512] + r*gn);
                float hold = hsm[(s0+i)*260 + jg0 + j];
                float hnew = (1.f - z)*n + z*hold;
                y[base*512 + dir*256 + jg0 + j] = hnew;
                hout[(s0+i)*256 + jg0 + j] = hnew;
            }
        }
        // group barrier: release fence -> atomic arrive -> atomic-RMW acquire poll.
        // NOTE: poll MUST be an atomic RMW with a side-effecting body — a plain
        // __ldcg poll in an empty loop gets hoisted/deleted by the compiler (UB
        // infinite loop), silently removing the barrier (R3 failure).
        __threadfence();
        __syncthreads();
        if (tid == 0) {
            atomicAdd(barp, 1u);
            unsigned int tgt = (unsigned int)(t + 1) * 16u;
            while (atomicAdd(barp, 0u) < tgt) __nanosleep(32);
            __threadfence();
        }
        __syncthreads();
    }
}

// ----------------- top-k pooling + classifier -----------------
__global__ __launch_bounds__(256)
void halt_pool(const float* __restrict__ H, const int* __restrict__ lengths,
               const float* __restrict__ Wc, const float* __restrict__ bc,
               float* __restrict__ out) {
    int b = blockIdx.x, tid = threadIdx.x;
    __shared__ float ns[512];
    __shared__ int   si[512];
    __shared__ float red[256];
    int len = lengths[b];
    int warp = tid >> 5, lane = tid & 31;
    for (int r = warp; r < 512; r += 8) {
        float sc = 1e9f;
        if (r < len) {
            const float* row = H + ((size_t)b*512 + r)*512;
            float acc = 0.f;
#pragma unroll 4
            for (int d = lane; d < 512; d += 32) { float v = row[d]; acc += v*v; }
#pragma unroll
            for (int o = 16; o > 0; o >>= 1) acc += __shfl_xor_sync(0xffffffffu, acc, o);
            sc = -sqrtf(acc);                    // ascending by -score == descending score
        }
        if (lane == 0) { ns[r] = sc; si[r] = r; }
    }
    __syncthreads();
    for (int k = 2; k <= 512; k <<= 1)
        for (int j = k >> 1; j > 0; j >>= 1) {
            for (int i = tid; i < 512; i += 256) {
                int ixj = i ^ j;
                if (ixj > i) {
                    bool asc = ((i & k) == 0);
                    float a = ns[i], c = ns[ixj];
                    int ia = si[i], ic = si[ixj];
                    bool gt = (a > c) || (a == c && ia > ic);   // stable tie-break
                    if (asc == gt) { ns[i] = c; ns[ixj] = a; si[i] = ic; si[ixj] = ia; }
                }
            }
            __syncthreads();
        }
    int kk = (int)ceilf((float)len * 0.15f);
    if (kk < 1) kk = 1;
    float a0 = 0.f, a1 = 0.f;
    for (int i = 0; i < kk; i++) {
        int r = si[i];
        const float* row = H + ((size_t)b*512 + r)*512;
        a0 += row[tid]; a1 += row[tid + 256];
    }
    float kf = (float)kk;
    float part = (a0/kf)*Wc[tid] + (a1/kf)*Wc[tid + 256];
    red[tid] = part;
    __syncthreads();
    for (int s2 = 128; s2 > 0; s2 >>= 1) {
        if (tid < s2) red[tid] += red[tid + s2];
        __syncthreads();
    }
    if (tid == 0) out[b] = red[0] + bc[0];
}

// ----------------- host orchestration -----------------
extern "C" void kernel_launch(void* const* d_in, const int* in_sizes, int n_in,
                              void* d_out, int out_size) {
    const float* x    = (const float*)d_in[0];
    const int*   lens = (const int*)  d_in[1];
    const float* ln_g = (const float*)d_in[2];
    const float* ln_b = (const float*)d_in[3];
    const float* w1   = (const float*)d_in[4];
    const float* b1   = (const float*)d_in[5];
    const float* w2   = (const float*)d_in[6];
    const float* b2   = (const float*)d_in[7];
    const float* Wih0 = (const float*)d_in[8];
    const float* Whh0 = (const float*)d_in[9];
    const float* bih0 = (const float*)d_in[10];
    const float* bhh0 = (const float*)d_in[11];
    const float* Wih  = (const float*)d_in[12];
    const float* Whh  = (const float*)d_in[13];
    const float* bih  = (const float*)d_in[14];
    const float* bhh  = (const float*)d_in[15];
    const float* Wc   = (const float*)d_in[16];
    const float* bc   = (const float*)d_in[17];
    float* out = (float*)d_out;

    cudaFuncSetAttribute(halt_gru, cudaFuncAttributeMaxDynamicSharedMemorySize, GRU_SMEM);

    void *barp = 0, *hp = 0, *pA = 0, *pB = 0, *pxw = 0;
    cudaGetSymbolAddress(&barp, g_bar);
    cudaGetSymbolAddress(&hp,   g_h);
    cudaGetSymbolAddress(&pA,   g_bufA);
    cudaGetSymbolAddress(&pB,   g_bufB);
    cudaGetSymbolAddress(&pxw,  g_xw);
    float* fA  = (float*)pA;
    float* fB  = (float*)pB;
    float* fxw = (float*)pxw;

    halt_sort_perm<<<1, 256>>>(lens);
    halt_proj<<<NT, 128>>>(x, lens, ln_g, ln_b, w1, b1, w2, b2);

    dim3 gg(NT/128, 12);
    for (int l = 0; l < 5; l++) {
        const float* Wi = l ? (Wih + (size_t)(l-1)*2*768*512) : Wih0;
        const float* bi = l ? (bih + (l-1)*1536) : bih0;
        const float* Wh = l ? (Whh + (size_t)(l-1)*2*768*256) : Whh0;
        const float* bh = l ? (bhh + (l-1)*1536) : bhh0;
        int K = l ? 512 : 128;
        float* Ain  = (l & 1) ? fB : fA;
        float* Yout = (l & 1) ? fA : fB;
        cudaMemsetAsync(barp, 0, 16*sizeof(unsigned int));
        cudaMemsetAsync(hp,   0, (size_t)2*2*256*256*sizeof(float));
        halt_sgemm<<<gg, 256>>>(Ain, K, Wi, bi, fxw, lens);
        halt_gru<<<256, 128, GRU_SMEM>>>(fxw, Yout, Wh, bh, lens);
    }
    halt_pool<<<256, 256>>>(fB, lens, Wc, bc, out);
}

// round 7
// speedup vs baseline: 1.6990x; 1.0458x over previous
#include <cuda_runtime.h>
#include <cuda_bf16.h>
#include <math.h>
#include <stdint.h>

#define Bn   256
#define Tn   512
#define NT   (Bn*Tn)          // 131072 tokens

// GRU smem: Wsm [3][16][258] + hsm [32][260]
#define WSM_FLOATS (3*16*258)            // 12384
#define HSM_FLOATS (32*260)              // 8320
#define GRU_SMEM   ((WSM_FLOATS + HSM_FLOATS)*4)   // 82816 bytes

// MMA GEMM smem: 4 tiles of [128][64] bf16 (SW128 swizzled) + bias
#define OFF_AH   0
#define OFF_AL   16384
#define OFF_BH   32768
#define OFF_BL   49152
#define OFF_BIAS 65536
#define SMEM_TC  (65536 + 512)

// ----------------- device scratch (bss-zeroed at module load) -----------------
__device__ float g_xw  [(size_t)NT*1536];   // input-gate precompute, reused per layer
__device__ float g_bufA[(size_t)NT*512];    // activations ping (layer0 packed [NT][128])
__device__ float g_bufB[(size_t)NT*512];    // activations pong
__device__ float g_h   [2*2*256*256];       // h ping-pong: [pp][dir][sample(perm)][256]
__device__ unsigned int g_bar[16];          // per-(dir,btile) barrier counters
__device__ int   g_perm[256];               // batch order sorted by length desc
__device__ __nv_bfloat16 g_ah[(size_t)NT*512];   // A hi split
__device__ __nv_bfloat16 g_al[(size_t)NT*512];   // A lo split
__device__ __nv_bfloat16 g_wh[1536*512];         // W hi split
__device__ __nv_bfloat16 g_wl[1536*512];         // W lo split

// ----------------- packed f32x2 helpers (Blackwell FFMA2) -----------------
__device__ __forceinline__ unsigned long long pk2(float lo, float hi) {
    unsigned long long r;
    asm("mov.b64 %0, {%1, %2};" : "=l"(r) : "f"(lo), "f"(hi));
    return r;
}
__device__ __forceinline__ void fma2(unsigned long long &d, unsigned long long a, unsigned long long b) {
    asm("fma.rn.f32x2 %0, %1, %2, %0;" : "+l"(d) : "l"(a), "l"(b));
}
__device__ __forceinline__ float2 upk2(unsigned long long v) {
    float2 f;
    asm("mov.b64 {%0, %1}, %2;" : "=f"(f.x), "=f"(f.y) : "l"(v));
    return f;
}

// ----------------- mma.sync helpers (base ISA, compiles at compute_103) -----------------
__device__ __forceinline__ uint32_t smem_u32(const void* p) {
    uint32_t a;
    asm("{ .reg .u64 t; cvta.to.shared.u64 t, %1; cvt.u32.u64 %0, t; }" : "=r"(a) : "l"(p));
    return a;
}
#define SWIZ128(b) ((b) ^ (((b) >> 3) & 0x70))

__device__ __forceinline__ void ldsm4(uint32_t* r, uint32_t addr) {
    asm volatile("ldmatrix.sync.aligned.m8n8.x4.shared.b16 {%0,%1,%2,%3}, [%4];"
                 : "=r"(r[0]), "=r"(r[1]), "=r"(r[2]), "=r"(r[3]) : "r"(addr));
}
__device__ __forceinline__ void mma16816(float* c, const uint32_t* a, const uint32_t* b) {
    asm volatile("mma.sync.aligned.m16n8k16.row.col.f32.bf16.bf16.f32 "
                 "{%0,%1,%2,%3}, {%4,%5,%6,%7}, {%8,%9}, {%0,%1,%2,%3};"
                 : "+f"(c[0]), "+f"(c[1]), "+f"(c[2]), "+f"(c[3])
                 : "r"(a[0]), "r"(a[1]), "r"(a[2]), "r"(a[3]), "r"(b[0]), "r"(b[1]));
}

// ----------------- sort batch indices by length descending -----------------
__global__ void halt_sort_perm(const int* __restrict__ lengths) {
    __shared__ int key[256];
    __shared__ int idx[256];
    int tid = threadIdx.x;
    key[tid] = -lengths[tid];
    idx[tid] = tid;
    __syncthreads();
    for (int k = 2; k <= 256; k <<= 1)
        for (int j = k >> 1; j > 0; j >>= 1) {
            int ixj = tid ^ j;
            if (ixj > tid) {
                bool asc = ((tid & k) == 0);
                int a = key[tid], c = key[ixj];
                bool gt = a > c;
                if (asc == gt) {
                    key[tid] = c; key[ixj] = a;
                    int t2 = idx[tid]; idx[tid] = idx[ixj]; idx[ixj] = t2;
                }
            }
            __syncthreads();
        }
    g_perm[tid] = idx[tid];
}

// ----------------- input projection: LN -> Linear(25->128) -> GELU -> Linear(128->128) -----------------
__global__ void halt_proj(const float* __restrict__ x, const int* __restrict__ lengths,
                          const float* __restrict__ ln_g, const float* __restrict__ ln_b,
                          const float* __restrict__ w1, const float* __restrict__ b1,
                          const float* __restrict__ w2, const float* __restrict__ b2) {
    int token = blockIdx.x;
    int b = token >> 9, t = token & 511;
    if (t >= lengths[b]) return;
    __shared__ float sx[25], sn[25], sh1[128];
    int tid = threadIdx.x;
    if (tid < 25) sx[tid] = x[(size_t)token*25 + tid];
    __syncthreads();
    float mu = 0.f;
#pragma unroll
    for (int i = 0; i < 25; i++) mu += sx[i];
    mu *= (1.0f/25.0f);
    float var = 0.f;
#pragma unroll
    for (int i = 0; i < 25; i++) { float d = sx[i]-mu; var += d*d; }
    var *= (1.0f/25.0f);
    float rstd = rsqrtf(var + 1e-5f);
    if (tid < 25) sn[tid] = (sx[tid]-mu)*rstd*ln_g[tid] + ln_b[tid];
    __syncthreads();
    float a = b1[tid];
#pragma unroll
    for (int i = 0; i < 25; i++) a += sn[i]*w1[i*128 + tid];
    float ge = 0.5f*a*(1.0f + erff(a*0.70710678118654752440f));
    sh1[tid] = ge;
    __syncthreads();
    float o = b2[tid];
#pragma unroll 8
    for (int i = 0; i < 128; i++) o += sh1[i]*__ldg(&w2[i*128 + tid]);
    g_bufA[(size_t)token*128 + tid] = o;
}

// ----------------- fp32 -> bf16 hi/lo split -----------------
__global__ void halt_cvt(const float* __restrict__ src, __nv_bfloat16* __restrict__ hi,
                         __nv_bfloat16* __restrict__ lo, size_t n) {
    size_t i = (size_t)blockIdx.x*256 + threadIdx.x;
    if (i >= n) return;
    float v = src[i];
    __nv_bfloat16 h = __float2bfloat16(v);
    hi[i] = h;
    lo[i] = __float2bfloat16(v - __bfloat162float(h));
}

// ----------------- mma.sync GEMM: g_xw[M,1536] = A[M,K]*W[1536,K]^T + bias -----------------
// bf16 hi/lo split (3 mma chains). 128x128 block tile, K-chunk 64, 8 warps 32x64.
__global__ __launch_bounds__(256)
void halt_tcgemm(int K, const float* __restrict__ bias, const int* __restrict__ lengths) {
    int m0 = blockIdx.x * 128;
    int n0 = blockIdx.y * 128;
    if ((m0 & 511) >= lengths[m0 >> 9]) return;   // fully-padded tile: outputs never read
    extern __shared__ char smem[];
    uint32_t sb = smem_u32(smem);
    int tid = threadIdx.x, warp = tid >> 5, lane = tid & 31;
    int wm = warp & 3, wn = warp >> 2;             // 4 x 2 warp grid, tile 32x64

    if (tid < 128) ((float*)(smem + OFF_BIAS))[tid] = bias[n0 + tid];

    const uint4* pAh = (const uint4*)g_ah;
    const uint4* pAl = (const uint4*)g_al;
    const uint4* pBh = (const uint4*)g_wh;
    const uint4* pBl = (const uint4*)g_wl;

    float acc[2][8][4];
#pragma unroll
    for (int mi = 0; mi < 2; mi++)
#pragma unroll
        for (int ni = 0; ni < 8; ni++)
#pragma unroll
            for (int q = 0; q < 4; q++) acc[mi][ni][q] = 0.f;

    // ldmatrix source addresses (col varies with ks; base row part fixed)
    int arow = wm*32 + (lane & 15);                 // + mi*16
    int acolsel = (lane >> 4) * 8;
    int brow = wn*64 + (lane & 7) + ((lane & 16) ? 8 : 0);   // + p*16
    int bcolsel = (lane & 8) ? 8 : 0;

    int nchunks = K >> 6;
    for (int c = 0; c < nchunks; c++) {
        int k0 = c << 6;
        // stage 4 tiles [128 rows][64 bf16], SW128 swizzled, 16B units
        for (int it = tid; it < 1024; it += 256) {
            int r = it >> 3, u = it & 7;
            uint32_t sw = SWIZ128((uint32_t)(r*128 + u*16));
            size_t ga = ((size_t)(m0 + r)*K + k0) / 8 + u;
            size_t gb = ((size_t)(n0 + r)*K + k0) / 8 + u;
            *(uint4*)(smem + OFF_AH + sw) = pAh[ga];
            *(uint4*)(smem + OFF_AL + sw) = pAl[ga];
            *(uint4*)(smem + OFF_BH + sw) = pBh[gb];
            *(uint4*)(smem + OFF_BL + sw) = pBl[gb];
        }
        __syncthreads();
#pragma unroll
        for (int ks = 0; ks < 4; ks++) {
            int kc = ks*16;
            uint32_t ah[2][4], al[2][4];
#pragma unroll
            for (int mi = 0; mi < 2; mi++) {
                uint32_t off = SWIZ128((uint32_t)((arow + mi*16)*128 + (kc + acolsel)*2));
                ldsm4(ah[mi], sb + OFF_AH + off);
                ldsm4(al[mi], sb + OFF_AL + off);
            }
            uint32_t bh[4][4], bl[4][4];
#pragma unroll
            for (int p = 0; p < 4; p++) {
                uint32_t off = SWIZ128((uint32_t)((brow + p*16)*128 + (kc + bcolsel)*2));
                ldsm4(bh[p], sb + OFF_BH + off);
                ldsm4(bl[p], sb + OFF_BL + off);
            }
#pragma unroll
            for (int mi = 0; mi < 2; mi++)
#pragma unroll
                for (int p = 0; p < 4; p++) {
                    mma16816(acc[mi][2*p],   ah[mi], &bh[p][0]);
                    mma16816(acc[mi][2*p],   ah[mi], &bl[p][0]);
                    mma16816(acc[mi][2*p],   al[mi], &bh[p][0]);
                    mma16816(acc[mi][2*p+1], ah[mi], &bh[p][2]);
                    mma16816(acc[mi][2*p+1], ah[mi], &bl[p][2]);
                    mma16816(acc[mi][2*p+1], al[mi], &bh[p][2]);
                }
        }
        __syncthreads();
    }

    // epilogue: c0,c1 -> row r, cols 2c,2c+1 ; c2,c3 -> row r+8
    const float* sbias = (const float*)(smem + OFF_BIAS);
#pragma unroll
    for (int mi = 0; mi < 2; mi++) {
        int rw = m0 + wm*32 + mi*16 + (lane >> 2);
#pragma unroll
        for (int ni = 0; ni < 8; ni++) {
            int cw = wn*64 + ni*8 + (lane & 3)*2;
            float bx = sbias[cw], by = sbias[cw + 1];
            float2 v0 = { acc[mi][ni][0] + bx, acc[mi][ni][1] + by };
            float2 v1 = { acc[mi][ni][2] + bx, acc[mi][ni][3] + by };
            *(float2*)&g_xw[(size_t)rw*1536 + n0 + cw]       = v0;
            *(float2*)&g_xw[(size_t)(rw + 8)*1536 + n0 + cw] = v1;
        }
    }
}

// ----------------- persistent GRU layer: 256 blocks = dir(2) x hc(16) x bt(8) -----------------
__global__ __launch_bounds__(128)
void halt_gru(const float* __restrict__ xw, float* __restrict__ y,
              const float* __restrict__ Whh, const float* __restrict__ bhh,
              const int* __restrict__ lengths) {
    extern __shared__ float sm[];
    float* Wsm = sm;               // [3][16][258]: Wsm[(g*16+jj)*258 + k]
    float* hsm = sm + WSM_FLOATS;  // [32][260]:    hsm[s*260 + k]
    int bid = blockIdx.x;
    int dir = bid >> 7;
    int hc  = (bid >> 3) & 15;
    int bt  = bid & 7;
    int jg0 = hc * 16;
    int tid = threadIdx.x;
    int j = tid & 15, sg = tid >> 4, s0 = sg * 4;

    const float* Wd = Whh + (size_t)dir*768*256;
    for (int it = tid; it < 3*16*256; it += 128) {
        int k = it & 255, jj = (it >> 8) & 15, g = it >> 12;
        Wsm[(g*16 + jj)*258 + k] = Wd[(size_t)(g*256 + jg0 + jj)*256 + k];
    }
    float bh_r = bhh[dir*768 +       jg0 + j];
    float bh_z = bhh[dir*768 + 256 + jg0 + j];
    float bh_n = bhh[dir*768 + 512 + jg0 + j];
    int pb[4], lenv[4];
#pragma unroll
    for (int i = 0; i < 4; i++) {
        pb[i]   = g_perm[bt*32 + s0 + i];
        lenv[i] = lengths[pb[i]];
    }
    int tmax = lengths[g_perm[bt*32]];
    int grp = dir*8 + bt;
    unsigned int* barp = &g_bar[grp];
    __syncthreads();

    const float* Wr = Wsm + j*258;
    const float* Wz = Wsm + 16*258 + j*258;
    const float* Wn = Wsm + 32*258 + j*258;

    for (int t = 0; t < tmax; t++) {
        const float* hin = g_h + ((size_t)((t & 1)*2 + dir)*256 + bt*32)*256;
        for (int it = tid; it < 2048; it += 128) {
            int s = it >> 6, f = (it & 63)*4;
            float4 v = __ldcg((const float4*)&hin[s*256 + f]);
            *(float4*)&hsm[s*260 + f] = v;
        }
        __syncthreads();

        unsigned long long ar[4] = {0,0,0,0}, az[4] = {0,0,0,0}, an[4] = {0,0,0,0};
#pragma unroll 4
        for (int kp = 0; kp < 128; kp++) {
            int k2 = kp*2;
            unsigned long long wr = *(const unsigned long long*)&Wr[k2];
            unsigned long long wz = *(const unsigned long long*)&Wz[k2];
            unsigned long long wn = *(const unsigned long long*)&Wn[k2];
#pragma unroll
            for (int i = 0; i < 4; i++) {
                unsigned long long hp = *(const unsigned long long*)&hsm[(s0+i)*260 + k2];
                fma2(ar[i], wr, hp); fma2(az[i], wz, hp); fma2(an[i], wn, hp);
            }
        }

        float* hout = g_h + ((size_t)(((t+1) & 1)*2 + dir)*256 + bt*32)*256;
#pragma unroll
        for (int i = 0; i < 4; i++) {
            if (t < lenv[i]) {
                float2 rr = upk2(ar[i]), zz = upk2(az[i]), nn = upk2(an[i]);
                float gr = rr.x + rr.y + bh_r;
                float gz = zz.x + zz.y + bh_z;
                float gn = nn.x + nn.y + bh_n;
                int tok = dir ? (lenv[i] - 1 - t) : t;
                size_t base = (size_t)pb[i]*512 + tok;
                const float* xp = xw + base*1536 + dir*768 + jg0 + j;
                float r = 1.f/(1.f + expf(-(xp[0]   + gr)));
                float z = 1.f/(1.f + expf(-(xp[256] + gz)));
                float n = tanhf(xp[512] + r*gn);
                float hold = hsm[(s0+i)*260 + jg0 + j];
                float hnew = (1.f - z)*n + z*hold;
                y[base*512 + dir*256 + jg0 + j] = hnew;
                hout[(s0+i)*256 + jg0 + j] = hnew;
            }
        }
        // group barrier: release fence -> atomic arrive -> atomic-RMW acquire poll.
        // Poll MUST be an atomic RMW (plain load poll gets deleted as UB -> R3 failure).
        __threadfence();
        __syncthreads();
        if (tid == 0) {
            atomicAdd(barp, 1u);
            unsigned int tgt = (unsigned int)(t + 1) * 16u;
            while (atomicAdd(barp, 0u) < tgt) __nanosleep(32);
            __threadfence();
        }
        __syncthreads();
    }
}

// ----------------- top-k pooling + classifier -----------------
__global__ __launch_bounds__(256)
void halt_pool(const float* __restrict__ H, const int* __restrict__ lengths,
               const float* __restrict__ Wc, const float* __restrict__ bc,
               float* __restrict__ out) {
    int b = blockIdx.x, tid = threadIdx.x;
    __shared__ float ns[512];
    __shared__ int   si[512];
    __shared__ float red[256];
    int len = lengths[b];
    int warp = tid >> 5, lane = tid & 31;
    for (int r = warp; r < 512; r += 8) {
        float sc = 1e9f;
        if (r < len) {
            const float* row = H + ((size_t)b*512 + r)*512;
            float acc = 0.f;
#pragma unroll 4
            for (int d = lane; d < 512; d += 32) { float v = row[d]; acc += v*v; }
#pragma unroll
            for (int o = 16; o > 0; o >>= 1) acc += __shfl_xor_sync(0xffffffffu, acc, o);
            sc = -sqrtf(acc);
        }
        if (lane == 0) { ns[r] = sc; si[r] = r; }
    }
    __syncthreads();
    for (int k = 2; k <= 512; k <<= 1)
        for (int j = k >> 1; j > 0; j >>= 1) {
            for (int i = tid; i < 512; i += 256) {
                int ixj = i ^ j;
                if (ixj > i) {
                    bool asc = ((i & k) == 0);
                    float a = ns[i], c = ns[ixj];
                    int ia = si[i], ic = si[ixj];
                    bool gt = (a > c) || (a == c && ia > ic);
                    if (asc == gt) { ns[i] = c; ns[ixj] = a; si[i] = ic; si[ixj] = ia; }
                }
            }
            __syncthreads();
        }
    int kk = (int)ceilf((float)len * 0.15f);
    if (kk < 1) kk = 1;
    float a0 = 0.f, a1 = 0.f;
    for (int i = 0; i < kk; i++) {
        int r = si[i];
        const float* row = H + ((size_t)b*512 + r)*512;
        a0 += row[tid]; a1 += row[tid + 256];
    }
    float kf = (float)kk;
    float part = (a0/kf)*Wc[tid] + (a1/kf)*Wc[tid + 256];
    red[tid] = part;
    __syncthreads();
    for (int s2 = 128; s2 > 0; s2 >>= 1) {
        if (tid < s2) red[tid] += red[tid + s2];
        __syncthreads();
    }
    if (tid == 0) out[b] = red[0] + bc[0];
}

// ----------------- host orchestration -----------------
extern "C" void kernel_launch(void* const* d_in, const int* in_sizes, int n_in,
                              void* d_out, int out_size) {
    const float* x    = (const float*)d_in[0];
    const int*   lens = (const int*)  d_in[1];
    const float* ln_g = (const float*)d_in[2];
    const float* ln_b = (const float*)d_in[3];
    const float* w1   = (const float*)d_in[4];
    const float* b1   = (const float*)d_in[5];
    const float* w2   = (const float*)d_in[6];
    const float* b2   = (const float*)d_in[7];
    const float* Wih0 = (const float*)d_in[8];
    const float* Whh0 = (const float*)d_in[9];
    const float* bih0 = (const float*)d_in[10];
    const float* bhh0 = (const float*)d_in[11];
    const float* Wih  = (const float*)d_in[12];
    const float* Whh  = (const float*)d_in[13];
    const float* bih  = (const float*)d_in[14];
    const float* bhh  = (const float*)d_in[15];
    const float* Wc   = (const float*)d_in[16];
    const float* bc   = (const float*)d_in[17];
    float* out = (float*)d_out;

    cudaFuncSetAttribute(halt_gru, cudaFuncAttributeMaxDynamicSharedMemorySize, GRU_SMEM);
    cudaFuncSetAttribute(halt_tcgemm, cudaFuncAttributeMaxDynamicSharedMemorySize, SMEM_TC);

    void *barp = 0, *hp = 0, *pA = 0, *pB = 0, *pxw = 0;
    void *pah = 0, *pal = 0, *pwh = 0, *pwl = 0;
    cudaGetSymbolAddress(&barp, g_bar);
    cudaGetSymbolAddress(&hp,   g_h);
    cudaGetSymbolAddress(&pA,   g_bufA);
    cudaGetSymbolAddress(&pB,   g_bufB);
    cudaGetSymbolAddress(&pxw,  g_xw);
    cudaGetSymbolAddress(&pah,  g_ah);
    cudaGetSymbolAddress(&pal,  g_al);
    cudaGetSymbolAddress(&pwh,  g_wh);
    cudaGetSymbolAddress(&pwl,  g_wl);
    float* fA = (float*)pA;
    float* fB = (float*)pB;
    float* fxw = (float*)pxw;

    halt_sort_perm<<<1, 256>>>(lens);
    halt_proj<<<NT, 128>>>(x, lens, ln_g, ln_b, w1, b1, w2, b2);

    for (int l = 0; l < 5; l++) {
        const float* Wi = l ? (Wih + (size_t)(l-1)*2*768*512) : Wih0;
        const float* bi = l ? (bih + (l-1)*1536) : bih0;
        const float* Wh = l ? (Whh + (size_t)(l-1)*2*768*256) : Whh0;
        const float* bh = l ? (bhh + (l-1)*1536) : bhh0;
        int K = l ? 512 : 128;
        float* Ain  = (l & 1) ? fB : fA;
        float* Yout = (l & 1) ? fA : fB;
        cudaMemsetAsync(barp, 0, 16*sizeof(unsigned int));
        cudaMemsetAsync(hp,   0, (size_t)2*2*256*256*sizeof(float));

        size_t nA = (size_t)NT * K;
        size_t nW = (size_t)1536 * K;
        halt_cvt<<<(unsigned)((nA + 255)/256), 256>>>(Ain, (__nv_bfloat16*)pah, (__nv_bfloat16*)pal, nA);
        halt_cvt<<<(unsigned)((nW + 255)/256), 256>>>(Wi,  (__nv_bfloat16*)pwh, (__nv_bfloat16*)pwl, nW);

        dim3 gg(NT/128, 12);
        halt_tcgemm<<<gg, 256, SMEM_TC>>>(K, bi, lens);

        halt_gru<<<256, 128, GRU_SMEM>>>(fxw, Yout, Wh, bh, lens);
    }
    halt_pool<<<256, 256>>>(fB, lens, Wc, bc, out);
}

// round 8
// speedup vs baseline: 3.1245x; 1.8390x over previous
#include <cuda_runtime.h>
#include <cuda_bf16.h>
#include <math.h>
#include <stdint.h>

#define Bn   256
#define Tn   512
#define NT   (Bn*Tn)          // 131072 tokens

// GRU2 smem: hsm [32][260] + psm [3][8][8][32]
#define GRU2_SMEM ((32*260 + 3*8*8*32)*4)   // 57856 bytes

// MMA GEMM smem: 4 tiles of [128][64] bf16 (SW128 swizzled) + bias
#define OFF_AH   0
#define OFF_AL   16384
#define OFF_BH   32768
#define OFF_BL   49152
#define OFF_BIAS 65536
#define SMEM_TC  (65536 + 512)

// ----------------- device scratch (bss-zeroed at module load) -----------------
__device__ float g_xw  [(size_t)NT*1536];   // input-gate precompute, reused per layer
__device__ float g_bufA[(size_t)NT*512];    // activations ping (layer0 packed [NT][128])
__device__ float g_bufB[(size_t)NT*512];    // activations pong
__device__ float g_h   [2*2*256*256];       // h ping-pong: [pp][dir][sample(perm)][256]
__device__ int   g_perm[256];               // batch order sorted by length desc
__device__ __nv_bfloat16 g_ah[(size_t)NT*512];   // A hi split
__device__ __nv_bfloat16 g_al[(size_t)NT*512];   // A lo split
__device__ __nv_bfloat16 g_wh[1536*512];         // W hi split
__device__ __nv_bfloat16 g_wl[1536*512];         // W lo split

// ----------------- packed f32x2 helpers (Blackwell FFMA2) -----------------
__device__ __forceinline__ unsigned long long pk2(float lo, float hi) {
    unsigned long long r;
    asm("mov.b64 %0, {%1, %2};" : "=l"(r) : "f"(lo), "f"(hi));
    return r;
}
__device__ __forceinline__ void fma2(unsigned long long &d, unsigned long long a, unsigned long long b) {
    asm("fma.rn.f32x2 %0, %1, %2, %0;" : "+l"(d) : "l"(a), "l"(b));
}
__device__ __forceinline__ float2 upk2(unsigned long long v) {
    float2 f;
    asm("mov.b64 {%0, %1}, %2;" : "=f"(f.x), "=f"(f.y) : "l"(v));
    return f;
}

// ----------------- mma.sync helpers (base ISA, compiles at compute_103) -----------------
__device__ __forceinline__ uint32_t smem_u32(const void* p) {
    uint32_t a;
    asm("{ .reg .u64 t; cvta.to.shared.u64 t, %1; cvt.u32.u64 %0, t; }" : "=r"(a) : "l"(p));
    return a;
}
#define SWIZ128(b) ((b) ^ (((b) >> 3) & 0x70))

__device__ __forceinline__ void ldsm4(uint32_t* r, uint32_t addr) {
    asm volatile("ldmatrix.sync.aligned.m8n8.x4.shared.b16 {%0,%1,%2,%3}, [%4];"
                 : "=r"(r[0]), "=r"(r[1]), "=r"(r[2]), "=r"(r[3]) : "r"(addr));
}
__device__ __forceinline__ void mma16816(float* c, const uint32_t* a, const uint32_t* b) {
    asm volatile("mma.sync.aligned.m16n8k16.row.col.f32.bf16.bf16.f32 "
                 "{%0,%1,%2,%3}, {%4,%5,%6,%7}, {%8,%9}, {%0,%1,%2,%3};"
                 : "+f"(c[0]), "+f"(c[1]), "+f"(c[2]), "+f"(c[3])
                 : "r"(a[0]), "r"(a[1]), "r"(a[2]), "r"(a[3]), "r"(b[0]), "r"(b[1]));
}

// ----------------- sort batch indices by length descending -----------------
__global__ void halt_sort_perm(const int* __restrict__ lengths) {
    __shared__ int key[256];
    __shared__ int idx[256];
    int tid = threadIdx.x;
    key[tid] = -lengths[tid];
    idx[tid] = tid;
    __syncthreads();
    for (int k = 2; k <= 256; k <<= 1)
        for (int j = k >> 1; j > 0; j >>= 1) {
            int ixj = tid ^ j;
            if (ixj > tid) {
                bool asc = ((tid & k) == 0);
                int a = key[tid], c = key[ixj];
                bool gt = a > c;
                if (asc == gt) {
                    key[tid] = c; key[ixj] = a;
                    int t2 = idx[tid]; idx[tid] = idx[ixj]; idx[ixj] = t2;
                }
            }
            __syncthreads();
        }
    g_perm[tid] = idx[tid];
}

// ----------------- input projection: LN -> Linear(25->128) -> GELU -> Linear(128->128) -----------------
__global__ void halt_proj(const float* __restrict__ x, const int* __restrict__ lengths,
                          const float* __restrict__ ln_g, const float* __restrict__ ln_b,
                          const float* __restrict__ w1, const float* __restrict__ b1,
                          const float* __restrict__ w2, const float* __restrict__ b2) {
    int token = blockIdx.x;
    int b = token >> 9, t = token & 511;
    if (t >= lengths[b]) return;
    __shared__ float sx[25], sn[25], sh1[128];
    int tid = threadIdx.x;
    if (tid < 25) sx[tid] = x[(size_t)token*25 + tid];
    __syncthreads();
    float mu = 0.f;
#pragma unroll
    for (int i = 0; i < 25; i++) mu += sx[i];
    mu *= (1.0f/25.0f);
    float var = 0.f;
#pragma unroll
    for (int i = 0; i < 25; i++) { float d = sx[i]-mu; var += d*d; }
    var *= (1.0f/25.0f);
    float rstd = rsqrtf(var + 1e-5f);
    if (tid < 25) sn[tid] = (sx[tid]-mu)*rstd*ln_g[tid] + ln_b[tid];
    __syncthreads();
    float a = b1[tid];
#pragma unroll
    for (int i = 0; i < 25; i++) a += sn[i]*w1[i*128 + tid];
    float ge = 0.5f*a*(1.0f + erff(a*0.70710678118654752440f));
    sh1[tid] = ge;
    __syncthreads();
    float o = b2[tid];
#pragma unroll 8
    for (int i = 0; i < 128; i++) o += sh1[i]*__ldg(&w2[i*128 + tid]);
    g_bufA[(size_t)token*128 + tid] = o;
}

// ----------------- fp32 -> bf16 hi/lo split -----------------
__global__ void halt_cvt(const float* __restrict__ src, __nv_bfloat16* __restrict__ hi,
                         __nv_bfloat16* __restrict__ lo, size_t n) {
    size_t i = (size_t)blockIdx.x*256 + threadIdx.x;
    if (i >= n) return;
    float v = src[i];
    __nv_bfloat16 h = __float2bfloat16(v);
    hi[i] = h;
    lo[i] = __float2bfloat16(v - __bfloat162float(h));
}

// ----------------- mma.sync GEMM: g_xw[M,1536] = A[M,K]*W[1536,K]^T + bias -----------------
__global__ __launch_bounds__(256)
void halt_tcgemm(int K, const float* __restrict__ bias, const int* __restrict__ lengths) {
    int m0 = blockIdx.x * 128;
    int n0 = blockIdx.y * 128;
    if ((m0 & 511) >= lengths[m0 >> 9]) return;   // fully-padded tile: outputs never read
    extern __shared__ char smem[];
    uint32_t sb = smem_u32(smem);
    int tid = threadIdx.x, warp = tid >> 5, lane = tid & 31;
    int wm = warp & 3, wn = warp >> 2;             // 4 x 2 warp grid, tile 32x64

    if (tid < 128) ((float*)(smem + OFF_BIAS))[tid] = bias[n0 + tid];

    const uint4* pAh = (const uint4*)g_ah;
    const uint4* pAl = (const uint4*)g_al;
    const uint4* pBh = (const uint4*)g_wh;
    const uint4* pBl = (const uint4*)g_wl;

    float acc[2][8][4];
#pragma unroll
    for (int mi = 0; mi < 2; mi++)
#pragma unroll
        for (int ni = 0; ni < 8; ni++)
#pragma unroll
            for (int q = 0; q < 4; q++) acc[mi][ni][q] = 0.f;

    int arow = wm*32 + (lane & 15);
    int acolsel = (lane >> 4) * 8;
    int brow = wn*64 + (lane & 7) + ((lane & 16) ? 8 : 0);
    int bcolsel = (lane & 8) ? 8 : 0;

    int nchunks = K >> 6;
    for (int c = 0; c < nchunks; c++) {
        int k0 = c << 6;
        for (int it = tid; it < 1024; it += 256) {
            int r = it >> 3, u = it & 7;
            uint32_t sw = SWIZ128((uint32_t)(r*128 + u*16));
            size_t ga = ((size_t)(m0 + r)*K + k0) / 8 + u;
            size_t gb = ((size_t)(n0 + r)*K + k0) / 8 + u;
            *(uint4*)(smem + OFF_AH + sw) = pAh[ga];
            *(uint4*)(smem + OFF_AL + sw) = pAl[ga];
            *(uint4*)(smem + OFF_BH + sw) = pBh[gb];
            *(uint4*)(smem + OFF_BL + sw) = pBl[gb];
        }
        __syncthreads();
#pragma unroll
        for (int ks = 0; ks < 4; ks++) {
            int kc = ks*16;
            uint32_t ah[2][4], al[2][4];
#pragma unroll
            for (int mi = 0; mi < 2; mi++) {
                uint32_t off = SWIZ128((uint32_t)((arow + mi*16)*128 + (kc + acolsel)*2));
                ldsm4(ah[mi], sb + OFF_AH + off);
                ldsm4(al[mi], sb + OFF_AL + off);
            }
            uint32_t bh[4][4], bl[4][4];
#pragma unroll
            for (int p = 0; p < 4; p++) {
                uint32_t off = SWIZ128((uint32_t)((brow + p*16)*128 + (kc + bcolsel)*2));
                ldsm4(bh[p], sb + OFF_BH + off);
                ldsm4(bl[p], sb + OFF_BL + off);
            }
#pragma unroll
            for (int mi = 0; mi < 2; mi++)
#pragma unroll
                for (int p = 0; p < 4; p++) {
                    mma16816(acc[mi][2*p],   ah[mi], &bh[p][0]);
                    mma16816(acc[mi][2*p],   ah[mi], &bl[p][0]);
                    mma16816(acc[mi][2*p],   al[mi], &bh[p][0]);
                    mma16816(acc[mi][2*p+1], ah[mi], &bh[p][2]);
                    mma16816(acc[mi][2*p+1], ah[mi], &bl[p][2]);
                    mma16816(acc[mi][2*p+1], al[mi], &bh[p][2]);
                }
        }
        __syncthreads();
    }

    const float* sbias = (const float*)(smem + OFF_BIAS);
#pragma unroll
    for (int mi = 0; mi < 2; mi++) {
        int rw = m0 + wm*32 + mi*16 + (lane >> 2);
#pragma unroll
        for (int ni = 0; ni < 8; ni++) {
            int cw = wn*64 + ni*8 + (lane & 3)*2;
            float bx = sbias[cw], by = sbias[cw + 1];
            float2 v0 = { acc[mi][ni][0] + bx, acc[mi][ni][1] + by };
            float2 v1 = { acc[mi][ni][2] + bx, acc[mi][ni][3] + by };
            *(float2*)&g_xw[(size_t)rw*1536 + n0 + cw]       = v0;
            *(float2*)&g_xw[(size_t)(rw + 8)*1536 + n0 + cw] = v1;
        }
    }
}

// ----------------- GRU v2: register weights + kc-split + cluster-8 barrier -----------------
// 128 blocks = 2 dir x 8 hc(32 j) x 8 bt(32 samples); cluster = 8 hc blocks of one (dir,bt).
// Block: 256 threads = 32 jj x 8 kc (k-chunks of 32). Thread holds Whh[3][j][kc-chunk] in regs.
__global__ __launch_bounds__(256, 1) __cluster_dims__(8, 1, 1)
void halt_gru2(const float* __restrict__ xw, float* __restrict__ y,
               const float* __restrict__ Whh, const float* __restrict__ bhh,
               const int* __restrict__ lengths) {
    extern __shared__ float sm[];
    float* hsm = sm;                  // [32][260]  h for 32 samples, all 256 k
    float* psm = sm + 32*260;         // [(g*8+kc)*8+s][32jj]  partial gh
    int grp = blockIdx.x >> 3;        // 16 groups = (dir, bt)
    int hc  = blockIdx.x & 7;         // cluster rank
    int dir = grp >> 3;
    int bt  = grp & 7;
    int j0  = hc * 32;
    int tid = threadIdx.x;
    int jj  = tid & 31;
    int kc  = tid >> 5;               // compute: k-chunk; reduction: sample slot

    // load this thread's weight slice into registers, packed over k-pairs
    unsigned long long wreg[3][16];
    const float* Wd = Whh + (size_t)dir*768*256;
#pragma unroll
    for (int g = 0; g < 3; g++) {
        const float* row = Wd + (size_t)(g*256 + j0 + jj)*256 + kc*32;
#pragma unroll
        for (int kp = 0; kp < 16; kp++) {
            float2 w = *(const float2*)&row[2*kp];
            wreg[g][kp] = pk2(w.x, w.y);
        }
    }
    float bh0 = bhh[dir*768 +       j0 + jj];
    float bh1 = bhh[dir*768 + 256 + j0 + jj];
    float bh2 = bhh[dir*768 + 512 + j0 + jj];

    int pb[4], lenv[4];
#pragma unroll
    for (int i = 0; i < 4; i++) {
        pb[i]   = g_perm[bt*32 + i*8 + kc];   // sample handled in reduction for sgi=i
        lenv[i] = lengths[pb[i]];
    }
    int tmax = lengths[g_perm[bt*32]];        // sorted desc -> tile max (same across cluster)

    for (int t = 0; t < tmax; t++) {
        // refill hsm [32][256] from global ping (written by whole cluster last step)
        const float* hin = g_h + ((size_t)((t & 1)*2 + dir)*256 + bt*32)*256;
        for (int it = tid; it < 2048; it += 256) {
            int s = it >> 6, f = (it & 63)*4;
            float4 v = __ldcg((const float4*)&hin[s*256 + f]);
            *(float4*)&hsm[s*260 + f] = v;
        }
        // prefetch xw gates for this thread's 4 reduction samples (hide DRAM latency)
        float xp0[4], xp1[4], xp2[4];
        int tok[4];
#pragma unroll
        for (int i = 0; i < 4; i++) {
            tok[i] = 0;
            if (t < lenv[i]) {
                tok[i] = dir ? (lenv[i] - 1 - t) : t;
                size_t base = (size_t)pb[i]*512 + tok[i];
                const float* xq = xw + base*1536 + dir*768 + j0 + jj;
                xp0[i] = __ldg(xq); xp1[i] = __ldg(xq + 256); xp2[i] = __ldg(xq + 512);
            }
        }
        __syncthreads();

#pragma unroll
        for (int sgi = 0; sgi < 4; sgi++) {
            // partial gh over this thread's 32-k chunk for 8 samples
            unsigned long long a0[8], a1[8], a2[8];
#pragma unroll
            for (int s = 0; s < 8; s++) { a0[s] = 0ull; a1[s] = 0ull; a2[s] = 0ull; }
            const float* hb = hsm + (sgi*8)*260 + kc*32;
#pragma unroll
            for (int kp = 0; kp < 16; kp++) {
                unsigned long long h2[8];
#pragma unroll
                for (int s = 0; s < 8; s++)
                    h2[s] = *(const unsigned long long*)&hb[s*260 + 2*kp];  // warp-broadcast LDS
#pragma unroll
                for (int s = 0; s < 8; s++) {
                    fma2(a0[s], wreg[0][kp], h2[s]);
                    fma2(a1[s], wreg[1][kp], h2[s]);
                    fma2(a2[s], wreg[2][kp], h2[s]);
                }
            }
#pragma unroll
            for (int s = 0; s < 8; s++) {
                float2 v0 = upk2(a0[s]), v1 = upk2(a1[s]), v2 = upk2(a2[s]);
                psm[((0*8 + kc)*8 + s)*32 + jj] = v0.x + v0.y;
                psm[((1*8 + kc)*8 + s)*32 + jj] = v1.x + v1.y;
                psm[((2*8 + kc)*8 + s)*32 + jj] = v2.x + v2.y;
            }
            __syncthreads();
            // reduction: thread (s=kc, jj) finalizes sample sgi*8+kc, hidden unit j0+jj
            if (t < lenv[sgi]) {
                int sloc = sgi*8 + kc;
                float gr = bh0, gz = bh1, gn = bh2;
#pragma unroll
                for (int c = 0; c < 8; c++) {
                    gr += psm[((0*8 + c)*8 + kc)*32 + jj];
                    gz += psm[((1*8 + c)*8 + kc)*32 + jj];
                    gn += psm[((2*8 + c)*8 + kc)*32 + jj];
                }
                float r = 1.f/(1.f + expf(-(xp0[sgi] + gr)));
                float z = 1.f/(1.f + expf(-(xp1[sgi] + gz)));
                float n = tanhf(xp2[sgi] + r*gn);
                float hold = hsm[sloc*260 + j0 + jj];
                float hnew = (1.f - z)*n + z*hold;
                size_t base = (size_t)pb[sgi]*512 + tok[sgi];
                y[base*512 + dir*256 + j0 + jj] = hnew;
                g_h[((size_t)(((t+1) & 1)*2 + dir)*256 + bt*32 + sloc)*256 + j0 + jj] = hnew;
            }
            __syncthreads();   // protect psm before next sgi overwrites
        }
        // cluster barrier: release our h stores, acquire peers' (orders global for cluster)
        asm volatile("barrier.cluster.arrive.aligned;" ::: "memory");
        asm volatile("barrier.cluster.wait.aligned;"   ::: "memory");
    }
}

// ----------------- top-k pooling + classifier -----------------
__global__ __launch_bounds__(256)
void halt_pool(const float* __restrict__ H, const int* __restrict__ lengths,
               const float* __restrict__ Wc, const float* __restrict__ bc,
               float* __restrict__ out) {
    int b = blockIdx.x, tid = threadIdx.x;
    __shared__ float ns[512];
    __shared__ int   si[512];
    __shared__ float red[256];
    int len = lengths[b];
    int warp = tid >> 5, lane = tid & 31;
    for (int r = warp; r < 512; r += 8) {
        float sc = 1e9f;
        if (r < len) {
            const float* row = H + ((size_t)b*512 + r)*512;
            float acc = 0.f;
#pragma unroll 4
            for (int d = lane; d < 512; d += 32) { float v = row[d]; acc += v*v; }
#pragma unroll
            for (int o = 16; o > 0; o >>= 1) acc += __shfl_xor_sync(0xffffffffu, acc, o);
            sc = -sqrtf(acc);
        }
        if (lane == 0) { ns[r] = sc; si[r] = r; }
    }
    __syncthreads();
    for (int k = 2; k <= 512; k <<= 1)
        for (int j = k >> 1; j > 0; j >>= 1) {
            for (int i = tid; i < 512; i += 256) {
                int ixj = i ^ j;
                if (ixj > i) {
                    bool asc = ((i & k) == 0);
                    float a = ns[i], c = ns[ixj];
                    int ia = si[i], ic = si[ixj];
                    bool gt = (a > c) || (a == c && ia > ic);
                    if (asc == gt) { ns[i] = c; ns[ixj] = a; si[i] = ic; si[ixj] = ia; }
                }
            }
            __syncthreads();
        }
    int kk = (int)ceilf((float)len * 0.15f);
    if (kk < 1) kk = 1;
    float a0 = 0.f, a1 = 0.f;
    for (int i = 0; i < kk; i++) {
        int r = si[i];
        const float* row = H + ((size_t)b*512 + r)*512;
        a0 += row[tid]; a1 += row[tid + 256];
    }
    float kf = (float)kk;
    float part = (a0/kf)*Wc[tid] + (a1/kf)*Wc[tid + 256];
    red[tid] = part;
    __syncthreads();
    for (int s2 = 128; s2 > 0; s2 >>= 1) {
        if (tid < s2) red[tid] += red[tid + s2];
        __syncthreads();
    }
    if (tid == 0) out[b] = red[0] + bc[0];
}

// ----------------- host orchestration -----------------
extern "C" void kernel_launch(void* const* d_in, const int* in_sizes, int n_in,
                              void* d_out, int out_size) {
    const float* x    = (const float*)d_in[0];
    const int*   lens = (const int*)  d_in[1];
    const float* ln_g = (const float*)d_in[2];
    const float* ln_b = (const float*)d_in[3];
    const float* w1   = (const float*)d_in[4];
    const float* b1   = (const float*)d_in[5];
    const float* w2   = (const float*)d_in[6];
    const float* b2   = (const float*)d_in[7];
    const float* Wih0 = (const float*)d_in[8];
    const float* Whh0 = (const float*)d_in[9];
    const float* bih0 = (const float*)d_in[10];
    const float* bhh0 = (const float*)d_in[11];
    const float* Wih  = (const float*)d_in[12];
    const float* Whh  = (const float*)d_in[13];
    const float* bih  = (const float*)d_in[14];
    const float* bhh  = (const float*)d_in[15];
    const float* Wc   = (const float*)d_in[16];
    const float* bc   = (const float*)d_in[17];
    float* out = (float*)d_out;

    cudaFuncSetAttribute(halt_gru2, cudaFuncAttributeMaxDynamicSharedMemorySize, GRU2_SMEM);
    cudaFuncSetAttribute(halt_tcgemm, cudaFuncAttributeMaxDynamicSharedMemorySize, SMEM_TC);

    void *hp = 0, *pA = 0, *pB = 0, *pxw = 0;
    void *pah = 0, *pal = 0, *pwh = 0, *pwl = 0;
    cudaGetSymbolAddress(&hp,   g_h);
    cudaGetSymbolAddress(&pA,   g_bufA);
    cudaGetSymbolAddress(&pB,   g_bufB);
    cudaGetSymbolAddress(&pxw,  g_xw);
    cudaGetSymbolAddress(&pah,  g_ah);
    cudaGetSymbolAddress(&pal,  g_al);
    cudaGetSymbolAddress(&pwh,  g_wh);
    cudaGetSymbolAddress(&pwl,  g_wl);
    float* fA = (float*)pA;
    float* fB = (float*)pB;
    float* fxw = (float*)pxw;

    halt_sort_perm<<<1, 256>>>(lens);
    halt_proj<<<NT, 128>>>(x, lens, ln_g, ln_b, w1, b1, w2, b2);

    for (int l = 0; l < 5; l++) {
        const float* Wi = l ? (Wih + (size_t)(l-1)*2*768*512) : Wih0;
        const float* bi = l ? (bih + (l-1)*1536) : bih0;
        const float* Wh = l ? (Whh + (size_t)(l-1)*2*768*256) : Whh0;
        const float* bh = l ? (bhh + (l-1)*1536) : bhh0;
        int K = l ? 512 : 128;
        float* Ain  = (l & 1) ? fB : fA;
        float* Yout = (l & 1) ? fA : fB;
        cudaMemsetAsync(hp, 0, (size_t)2*2*256*256*sizeof(float));

        size_t nA = (size_t)NT * K;
        size_t nW = (size_t)1536 * K;
        halt_cvt<<<(unsigned)((nA + 255)/256), 256>>>(Ain, (__nv_bfloat16*)pah, (__nv_bfloat16*)pal, nA);
        halt_cvt<<<(unsigned)((nW + 255)/256), 256>>>(Wi,  (__nv_bfloat16*)pwh, (__nv_bfloat16*)pwl, nW);

        dim3 gg(NT/128, 12);
        halt_tcgemm<<<gg, 256, SMEM_TC>>>(K, bi, lens);

        halt_gru2<<<128, 256, GRU2_SMEM>>>(fxw, Yout, Wh, bh, lens);
    }
    halt_pool<<<256, 256>>>(fB, lens, Wc, bc, out);
}

// round 9
// speedup vs baseline: 3.7323x; 1.1945x over previous
#include <cuda_runtime.h>
#include <cuda_bf16.h>
#include <math.h>
#include <stdint.h>

#define Bn   256
#define Tn   512
#define NT   (Bn*Tn)          // 131072 tokens

// MMA GEMM smem: 4 tiles of [128][64] bf16 (SW128 swizzled) + bias
#define OFF_AH   0
#define OFF_AL   16384
#define OFF_BH   32768
#define OFF_BL   49152
#define OFF_BIAS 65536
#define SMEM_TC  (65536 + 512)

// GRU3 smem (bytes)
#define OFF_WH   0                    // Whh hi  [4 chunks][128 rows][64] bf16
#define OFF_WL   65536                // Whh lo
#define OFF_AH2  131072               // h hi    [4 chunks][32 rows][64] bf16
#define OFF_AL2  147456               // h lo
#define OFF_HOLD 163840               // fp32 [32][33]
#define OFF_PSM  168064               // fp32 [32][100]
#define SMEM_G3  180864

// ----------------- device scratch (bss-zeroed at module load) -----------------
__device__ float g_xw  [(size_t)NT*1536];   // input-gate precompute, reused per layer
__device__ float g_bufB[(size_t)NT*512];    // final-layer fp32 activations (pool input)
__device__ float g_h   [2*2*256*256];       // h ping-pong: [pp][dir][sample(perm)][256]
__device__ int   g_perm[256];               // batch order sorted by length desc
__device__ __nv_bfloat16 g_ah[(size_t)NT*512];   // A hi split (GEMM input)
__device__ __nv_bfloat16 g_al[(size_t)NT*512];   // A lo split
__device__ __nv_bfloat16 g_wh[1536*512];         // W hi split
__device__ __nv_bfloat16 g_wl[1536*512];         // W lo split

// ----------------- mma.sync helpers (base ISA, compiles at compute_103) -----------------
__device__ __forceinline__ uint32_t smem_u32(const void* p) {
    uint32_t a;
    asm("{ .reg .u64 t; cvta.to.shared.u64 t, %1; cvt.u32.u64 %0, t; }" : "=r"(a) : "l"(p));
    return a;
}
#define SWIZ128(b) ((b) ^ (((b) >> 3) & 0x70))

__device__ __forceinline__ void ldsm4(uint32_t* r, uint32_t addr) {
    asm volatile("ldmatrix.sync.aligned.m8n8.x4.shared.b16 {%0,%1,%2,%3}, [%4];"
                 : "=r"(r[0]), "=r"(r[1]), "=r"(r[2]), "=r"(r[3]) : "r"(addr));
}
__device__ __forceinline__ void mma16816(float* c, const uint32_t* a, const uint32_t* b) {
    asm volatile("mma.sync.aligned.m16n8k16.row.col.f32.bf16.bf16.f32 "
                 "{%0,%1,%2,%3}, {%4,%5,%6,%7}, {%8,%9}, {%0,%1,%2,%3};"
                 : "+f"(c[0]), "+f"(c[1]), "+f"(c[2]), "+f"(c[3])
                 : "r"(a[0]), "r"(a[1]), "r"(a[2]), "r"(a[3]), "r"(b[0]), "r"(b[1]));
}

// ----------------- sort batch indices by length descending -----------------
__global__ void halt_sort_perm(const int* __restrict__ lengths) {
    __shared__ int key[256];
    __shared__ int idx[256];
    int tid = threadIdx.x;
    key[tid] = -lengths[tid];
    idx[tid] = tid;
    __syncthreads();
    for (int k = 2; k <= 256; k <<= 1)
        for (int j = k >> 1; j > 0; j >>= 1) {
            int ixj = tid ^ j;
            if (ixj > tid) {
                bool asc = ((tid & k) == 0);
                int a = key[tid], c = key[ixj];
                bool gt = a > c;
                if (asc == gt) {
                    key[tid] = c; key[ixj] = a;
                    int t2 = idx[tid]; idx[tid] = idx[ixj]; idx[ixj] = t2;
                }
            }
            __syncthreads();
        }
    g_perm[tid] = idx[tid];
}

// ----------------- input projection: LN -> Linear -> GELU -> Linear, writes bf16 hi/lo -----------------
__global__ void halt_proj(const float* __restrict__ x, const int* __restrict__ lengths,
                          const float* __restrict__ ln_g, const float* __restrict__ ln_b,
                          const float* __restrict__ w1, const float* __restrict__ b1,
                          const float* __restrict__ w2, const float* __restrict__ b2) {
    int token = blockIdx.x;
    int b = token >> 9, t = token & 511;
    if (t >= lengths[b]) return;
    __shared__ float sx[25], sn[25], sh1[128];
    int tid = threadIdx.x;
    if (tid < 25) sx[tid] = x[(size_t)token*25 + tid];
    __syncthreads();
    float mu = 0.f;
#pragma unroll
    for (int i = 0; i < 25; i++) mu += sx[i];
    mu *= (1.0f/25.0f);
    float var = 0.f;
#pragma unroll
    for (int i = 0; i < 25; i++) { float d = sx[i]-mu; var += d*d; }
    var *= (1.0f/25.0f);
    float rstd = rsqrtf(var + 1e-5f);
    if (tid < 25) sn[tid] = (sx[tid]-mu)*rstd*ln_g[tid] + ln_b[tid];
    __syncthreads();
    float a = b1[tid];
#pragma unroll
    for (int i = 0; i < 25; i++) a += sn[i]*w1[i*128 + tid];
    float ge = 0.5f*a*(1.0f + erff(a*0.70710678118654752440f));
    sh1[tid] = ge;
    __syncthreads();
    float o = b2[tid];
#pragma unroll 8
    for (int i = 0; i < 128; i++) o += sh1[i]*__ldg(&w2[i*128 + tid]);
    __nv_bfloat16 hbf = __float2bfloat16(o);
    g_ah[(size_t)token*128 + tid] = hbf;
    g_al[(size_t)token*128 + tid] = __float2bfloat16(o - __bfloat162float(hbf));
}

// ----------------- fp32 -> bf16 hi/lo split (weights only now) -----------------
__global__ void halt_cvt(const float* __restrict__ src, __nv_bfloat16* __restrict__ hi,
                         __nv_bfloat16* __restrict__ lo, size_t n) {
    size_t i = (size_t)blockIdx.x*256 + threadIdx.x;
    if (i >= n) return;
    float v = src[i];
    __nv_bfloat16 h = __float2bfloat16(v);
    hi[i] = h;
    lo[i] = __float2bfloat16(v - __bfloat162float(h));
}

// ----------------- mma.sync GEMM: g_xw[M,1536] = A[M,K]*W[1536,K]^T + bias -----------------
__global__ __launch_bounds__(256)
void halt_tcgemm(int K, const float* __restrict__ bias, const int* __restrict__ lengths) {
    int m0 = blockIdx.x * 128;
    int n0 = blockIdx.y * 128;
    if ((m0 & 511) >= lengths[m0 >> 9]) return;   // fully-padded tile: outputs never read
    extern __shared__ char smem[];
    uint32_t sb = smem_u32(smem);
    int tid = threadIdx.x, warp = tid >> 5, lane = tid & 31;
    int wm = warp & 3, wn = warp >> 2;             // 4 x 2 warp grid, tile 32x64

    if (tid < 128) ((float*)(smem + OFF_BIAS))[tid] = bias[n0 + tid];

    const uint4* pAh = (const uint4*)g_ah;
    const uint4* pAl = (const uint4*)g_al;
    const uint4* pBh = (const uint4*)g_wh;
    const uint4* pBl = (const uint4*)g_wl;

    float acc[2][8][4];
#pragma unroll
    for (int mi = 0; mi < 2; mi++)
#pragma unroll
        for (int ni = 0; ni < 8; ni++)
#pragma unroll
            for (int q = 0; q < 4; q++) acc[mi][ni][q] = 0.f;

    int arow = wm*32 + (lane & 15);
    int acolsel = (lane >> 4) * 8;
    int brow = wn*64 + (lane & 7) + ((lane & 16) ? 8 : 0);
    int bcolsel = (lane & 8) ? 8 : 0;

    int nchunks = K >> 6;
    for (int c = 0; c < nchunks; c++) {
        int k0 = c << 6;
        for (int it = tid; it < 1024; it += 256) {
            int r = it >> 3, u = it & 7;
            uint32_t sw = SWIZ128((uint32_t)(r*128 + u*16));
            size_t ga = ((size_t)(m0 + r)*K + k0) / 8 + u;
            size_t gb = ((size_t)(n0 + r)*K + k0) / 8 + u;
            *(uint4*)(smem + OFF_AH + sw) = pAh[ga];
            *(uint4*)(smem + OFF_AL + sw) = pAl[ga];
            *(uint4*)(smem + OFF_BH + sw) = pBh[gb];
            *(uint4*)(smem + OFF_BL + sw) = pBl[gb];
        }
        __syncthreads();
#pragma unroll
        for (int ks = 0; ks < 4; ks++) {
            int kc = ks*16;
            uint32_t ah[2][4], al[2][4];
#pragma unroll
            for (int mi = 0; mi < 2; mi++) {
                uint32_t off = SWIZ128((uint32_t)((arow + mi*16)*128 + (kc + acolsel)*2));
                ldsm4(ah[mi], sb + OFF_AH + off);
                ldsm4(al[mi], sb + OFF_AL + off);
            }
            uint32_t bh[4][4], bl[4][4];
#pragma unroll
            for (int p = 0; p < 4; p++) {
                uint32_t off = SWIZ128((uint32_t)((brow + p*16)*128 + (kc + bcolsel)*2));
                ldsm4(bh[p], sb + OFF_BH + off);
                ldsm4(bl[p], sb + OFF_BL + off);
            }
#pragma unroll
            for (int mi = 0; mi < 2; mi++)
#pragma unroll
                for (int p = 0; p < 4; p++) {
                    mma16816(acc[mi][2*p],   ah[mi], &bh[p][0]);
                    mma16816(acc[mi][2*p],   ah[mi], &bl[p][0]);
                    mma16816(acc[mi][2*p],   al[mi], &bh[p][0]);
                    mma16816(acc[mi][2*p+1], ah[mi], &bh[p][2]);
                    mma16816(acc[mi][2*p+1], ah[mi], &bl[p][2]);
                    mma16816(acc[mi][2*p+1], al[mi], &bh[p][2]);
                }
        }
        __syncthreads();
    }

    const float* sbias = (const float*)(smem + OFF_BIAS);
#pragma unroll
    for (int mi = 0; mi < 2; mi++) {
        int rw = m0 + wm*32 + mi*16 + (lane >> 2);
#pragma unroll
        for (int ni = 0; ni < 8; ni++) {
            int cw = wn*64 + ni*8 + (lane & 3)*2;
            float bx = sbias[cw], by = sbias[cw + 1];
            float2 v0 = { acc[mi][ni][0] + bx, acc[mi][ni][1] + by };
            float2 v1 = { acc[mi][ni][2] + bx, acc[mi][ni][3] + by };
            *(float2*)&g_xw[(size_t)rw*1536 + n0 + cw]       = v0;
            *(float2*)&g_xw[(size_t)(rw + 8)*1536 + n0 + cw] = v1;
        }
    }
}

// ----------------- GRU v3: HMMA recurrence, smem bf16 weights, cluster-8 barrier -----------------
// 128 blocks = 2 dir x 8 bt x 8 hc(32 j); cluster = 8 hc blocks of one (dir,bt).
// Per step: gh[32 s][96 gate-rows] = h[32,256] @ Whh_slice^T via m16n8k16 bf16 hi/lo 3-chain.
__global__ __launch_bounds__(256, 1) __cluster_dims__(8, 1, 1)
void halt_gru3(const float* __restrict__ xw, float* __restrict__ y,
               const float* __restrict__ Whh, const float* __restrict__ bhh,
               const int* __restrict__ lengths, int last) {
    extern __shared__ char smg[];
    uint32_t sb = smem_u32(smg);
    float* holdp = (float*)(smg + OFF_HOLD);   // [32][33]
    float* psm   = (float*)(smg + OFF_PSM);    // [32][100]
    int grp = blockIdx.x >> 3;
    int hc  = blockIdx.x & 7;
    int dir = grp >> 3;
    int bt  = grp & 7;
    int j0  = hc * 32;
    int tid = threadIdx.x;
    int warp = tid >> 5, lane = tid & 31;
    int wm = warp >> 2, wn = warp & 3;         // 2 m-tiles x 4 n-groups(24 cols)
    int jj = tid & 31, squad = tid >> 5;

    // load Whh slice -> smem bf16 hi/lo, [4 chunks][128 rows pad][64], SW128
    const float* Wd = Whh + (size_t)dir*768*256;
    for (int idx = tid; idx < 96*256; idx += 256) {
        int r = idx >> 8, k = idx & 255;
        int g = r >> 5, jl = r & 31;
        float w = Wd[(size_t)(g*256 + j0 + jl)*256 + k];
        __nv_bfloat16 h = __float2bfloat16(w);
        __nv_bfloat16 l = __float2bfloat16(w - __bfloat162float(h));
        int chunk = k >> 6;
        uint32_t sw = SWIZ128((uint32_t)(r*128 + (k & 63)*2));
        *(__nv_bfloat16*)(smg + OFF_WH + chunk*16384 + sw) = h;
        *(__nv_bfloat16*)(smg + OFF_WL + chunk*16384 + sw) = l;
    }
    float bh0 = bhh[dir*768 +       j0 + jj];
    float bh1 = bhh[dir*768 + 256 + j0 + jj];
    float bh2 = bhh[dir*768 + 512 + j0 + jj];
    int pb[4], lenv[4];
#pragma unroll
    for (int i = 0; i < 4; i++) {
        pb[i]   = g_perm[bt*32 + i*8 + squad];
        lenv[i] = lengths[pb[i]];
    }
    int tmax = lengths[g_perm[bt*32]];   // sorted desc -> tile max (same across cluster)
    __syncthreads();

    for (int t = 0; t < tmax; t++) {
        // prefetch xw gates for this thread's 4 elementwise samples
        float xp0[4], xp1[4], xp2[4];
        int tok[4];
#pragma unroll
        for (int i = 0; i < 4; i++) {
            tok[i] = 0;
            if (t < lenv[i]) {
                tok[i] = dir ? (lenv[i] - 1 - t) : t;
                size_t base = (size_t)pb[i]*512 + tok[i];
                const float* xq = xw + base*1536 + dir*768 + j0 + jj;
                xp0[i] = __ldg(xq); xp1[i] = __ldg(xq + 256); xp2[i] = __ldg(xq + 512);
            }
        }
        // phase 1: load h fp32 from global ping, split to bf16 A tiles + keep own j-slice fp32
        const float* hin = g_h + ((size_t)((t & 1)*2 + dir)*256 + bt*32)*256;
        for (int it = tid; it < 2048; it += 256) {
            int s = it >> 6, f = (it & 63)*4;
            float4 v = __ldcg((const float4*)&hin[s*256 + f]);
            __nv_bfloat16 h0 = __float2bfloat16(v.x), h1 = __float2bfloat16(v.y);
            __nv_bfloat16 h2 = __float2bfloat16(v.z), h3 = __float2bfloat16(v.w);
            __nv_bfloat16 l0 = __float2bfloat16(v.x - __bfloat162float(h0));
            __nv_bfloat16 l1 = __float2bfloat16(v.y - __bfloat162float(h1));
            __nv_bfloat16 l2 = __float2bfloat16(v.z - __bfloat162float(h2));
            __nv_bfloat16 l3 = __float2bfloat16(v.w - __bfloat162float(h3));
            uint2 hp, lp;
            hp.x = (uint32_t)__bfloat16_as_ushort(h0) | ((uint32_t)__bfloat16_as_ushort(h1) << 16);
            hp.y = (uint32_t)__bfloat16_as_ushort(h2) | ((uint32_t)__bfloat16_as_ushort(h3) << 16);
            lp.x = (uint32_t)__bfloat16_as_ushort(l0) | ((uint32_t)__bfloat16_as_ushort(l1) << 16);
            lp.y = (uint32_t)__bfloat16_as_ushort(l2) | ((uint32_t)__bfloat16_as_ushort(l3) << 16);
            int chunk = f >> 6;
            uint32_t sw = SWIZ128((uint32_t)(s*128 + (f & 63)*2));
            *(uint2*)(smg + OFF_AH2 + chunk*4096 + sw) = hp;
            *(uint2*)(smg + OFF_AL2 + chunk*4096 + sw) = lp;
            if (f >= j0 && f < j0 + 32) {
                float* hq = holdp + s*33 + (f - j0);
                hq[0] = v.x; hq[1] = v.y; hq[2] = v.z; hq[3] = v.w;
            }
        }
        __syncthreads();

        // phase 2: mma — warp: m16 tile wm, 3 n8 tiles at n0w
        float acc[3][4];
#pragma unroll
        for (int q = 0; q < 3; q++) { acc[q][0]=0.f; acc[q][1]=0.f; acc[q][2]=0.f; acc[q][3]=0.f; }
        int n0w = wn * 24;
        int arow = wm*16 + (lane & 15);
        int acolsel = (lane >> 4) * 8;
        int brow = n0w + (lane & 7) + ((lane & 16) ? 8 : 0);
        int bcolsel = (lane & 8) ? 8 : 0;
#pragma unroll
        for (int k16 = 0; k16 < 16; k16++) {
            int chunk = k16 >> 2, kc = (k16 & 3)*16;
            uint32_t asw = SWIZ128((uint32_t)(arow*128 + (kc + acolsel)*2));
            uint32_t ah[4], al[4];
            ldsm4(ah, sb + OFF_AH2 + chunk*4096 + asw);
            ldsm4(al, sb + OFF_AL2 + chunk*4096 + asw);
            uint32_t bsw0 = SWIZ128((uint32_t)(brow*128 + (kc + bcolsel)*2));
            uint32_t bsw1 = SWIZ128((uint32_t)((brow + 16)*128 + (kc + bcolsel)*2));
            uint32_t bh01[4], bh2x[4], bl01[4], bl2x[4];
            ldsm4(bh01, sb + OFF_WH + chunk*16384 + bsw0);
            ldsm4(bh2x, sb + OFF_WH + chunk*16384 + bsw1);   // t2 in regs [0,1]; [2,3] unused
            ldsm4(bl01, sb + OFF_WL + chunk*16384 + bsw0);
            ldsm4(bl2x, sb + OFF_WL + chunk*16384 + bsw1);
            mma16816(acc[0], ah, &bh01[0]); mma16816(acc[0], ah, &bl01[0]); mma16816(acc[0], al, &bh01[0]);
            mma16816(acc[1], ah, &bh01[2]); mma16816(acc[1], ah, &bl01[2]); mma16816(acc[1], al, &bh01[2]);
            mma16816(acc[2], ah, &bh2x[0]); mma16816(acc[2], ah, &bl2x[0]); mma16816(acc[2], al, &bh2x[0]);
        }

        // phase 3: dump fragments to psm[32][100]
        {
            int row = wm*16 + (lane >> 2);
#pragma unroll
            for (int q = 0; q < 3; q++) {
                int colb = n0w + q*8 + (lane & 3)*2;
                *(float2*)&psm[row*100 + colb]       = make_float2(acc[q][0], acc[q][1]);
                *(float2*)&psm[(row + 8)*100 + colb] = make_float2(acc[q][2], acc[q][3]);
            }
        }
        __syncthreads();

        // phase 4: elementwise gates; write h-pong + (bf16 A for next layer | fp32 y if last)
#pragma unroll
        for (int i = 0; i < 4; i++) {
            if (t < lenv[i]) {
                int s = i*8 + squad;
                float gr = psm[s*100 +      jj] + bh0;
                float gz = psm[s*100 + 32 + jj] + bh1;
                float gn = psm[s*100 + 64 + jj] + bh2;
                float r = 1.f/(1.f + expf(-(xp0[i] + gr)));
                float z = 1.f/(1.f + expf(-(xp1[i] + gz)));
                float n = tanhf(xp2[i] + r*gn);
                float hold = holdp[s*33 + jj];
                float hnew = (1.f - z)*n + z*hold;
                size_t base = (size_t)pb[i]*512 + tok[i];
                size_t oc = base*512 + dir*256 + j0 + jj;
                if (last) {
                    y[oc] = hnew;
                } else {
                    __nv_bfloat16 hb = __float2bfloat16(hnew);
                    g_ah[oc] = hb;
                    g_al[oc] = __float2bfloat16(hnew - __bfloat162float(hb));
                }
                g_h[((size_t)(((t+1) & 1)*2 + dir)*256 + bt*32 + s)*256 + j0 + jj] = hnew;
            }
        }
        // cluster barrier: release our h stores, acquire peers'
        asm volatile("barrier.cluster.arrive.aligned;" ::: "memory");
        asm volatile("barrier.cluster.wait.aligned;"   ::: "memory");
    }
}

// ----------------- top-k pooling + classifier -----------------
__global__ __launch_bounds__(256)
void halt_pool(const float* __restrict__ H, const int* __restrict__ lengths,
               const float* __restrict__ Wc, const float* __restrict__ bc,
               float* __restrict__ out) {
    int b = blockIdx.x, tid = threadIdx.x;
    __shared__ float ns[512];
    __shared__ int   si[512];
    __shared__ float red[256];
    int len = lengths[b];
    int warp = tid >> 5, lane = tid & 31;
    for (int r = warp; r < 512; r += 8) {
        float sc = 1e9f;
        if (r < len) {
            const float* row = H + ((size_t)b*512 + r)*512;
            float acc = 0.f;
#pragma unroll 4
            for (int d = lane; d < 512; d += 32) { float v = row[d]; acc += v*v; }
#pragma unroll
            for (int o = 16; o > 0; o >>= 1) acc += __shfl_xor_sync(0xffffffffu, acc, o);
            sc = -sqrtf(acc);
        }
        if (lane == 0) { ns[r] = sc; si[r] = r; }
    }
    __syncthreads();
    for (int k = 2; k <= 512; k <<= 1)
        for (int j = k >> 1; j > 0; j >>= 1) {
            for (int i = tid; i < 512; i += 256) {
                int ixj = i ^ j;
                if (ixj > i) {
                    bool asc = ((i & k) == 0);
                    float a = ns[i], c = ns[ixj];
                    int ia = si[i], ic = si[ixj];
                    bool gt = (a > c) || (a == c && ia > ic);
                    if (asc == gt) { ns[i] = c; ns[ixj] = a; si[i] = ic; si[ixj] = ia; }
                }
            }
            __syncthreads();
        }
    int kk = (int)ceilf((float)len * 0.15f);
    if (kk < 1) kk = 1;
    float a0 = 0.f, a1 = 0.f;
    for (int i = 0; i < kk; i++) {
        int r = si[i];
        const float* row = H + ((size_t)b*512 + r)*512;
        a0 += row[tid]; a1 += row[tid + 256];
    }
    float kf = (float)kk;
    float part = (a0/kf)*Wc[tid] + (a1/kf)*Wc[tid + 256];
    red[tid] = part;
    __syncthreads();
    for (int s2 = 128; s2 > 0; s2 >>= 1) {
        if (tid < s2) red[tid] += red[tid + s2];
        __syncthreads();
    }
    if (tid == 0) out[b] = red[0] + bc[0];
}

// ----------------- host orchestration -----------------
extern "C" void kernel_launch(void* const* d_in, const int* in_sizes, int n_in,
                              void* d_out, int out_size) {
    const float* x    = (const float*)d_in[0];
    const int*   lens = (const int*)  d_in[1];
    const float* ln_g = (const float*)d_in[2];
    const float* ln_b = (const float*)d_in[3];
    const float* w1   = (const float*)d_in[4];
    const float* b1   = (const float*)d_in[5];
    const float* w2   = (const float*)d_in[6];
    const float* b2   = (const float*)d_in[7];
    const float* Wih0 = (const float*)d_in[8];
    const float* Whh0 = (const float*)d_in[9];
    const float* bih0 = (const float*)d_in[10];
    const float* bhh0 = (const float*)d_in[11];
    const float* Wih  = (const float*)d_in[12];
    const float* Whh  = (const float*)d_in[13];
    const float* bih  = (const float*)d_in[14];
    const float* bhh  = (const float*)d_in[15];
    const float* Wc   = (const float*)d_in[16];
    const float* bc   = (const float*)d_in[17];
    float* out = (float*)d_out;

    cudaFuncSetAttribute(halt_gru3, cudaFuncAttributeMaxDynamicSharedMemorySize, SMEM_G3);
    cudaFuncSetAttribute(halt_tcgemm, cudaFuncAttributeMaxDynamicSharedMemorySize, SMEM_TC);

    void *hp = 0, *pB = 0, *pxw = 0, *pwh = 0, *pwl = 0;
    cudaGetSymbolAddress(&hp,  g_h);
    cudaGetSymbolAddress(&pB,  g_bufB);
    cudaGetSymbolAddress(&pxw, g_xw);
    cudaGetSymbolAddress(&pwh, g_wh);
    cudaGetSymbolAddress(&pwl, g_wl);
    float* fB  = (float*)pB;
    float* fxw = (float*)pxw;

    halt_sort_perm<<<1, 256>>>(lens);
    halt_proj<<<NT, 128>>>(x, lens, ln_g, ln_b, w1, b1, w2, b2);

    for (int l = 0; l < 5; l++) {
        const float* Wi = l ? (Wih + (size_t)(l-1)*2*768*512) : Wih0;
        const float* bi = l ? (bih + (l-1)*1536) : bih0;
        const float* Wh = l ? (Whh + (size_t)(l-1)*2*768*256) : Whh0;
        const float* bh = l ? (bhh + (l-1)*1536) : bhh0;
        int K = l ? 512 : 128;
        cudaMemsetAsync(hp, 0, (size_t)2*2*256*256*sizeof(float));

        size_t nW = (size_t)1536 * K;
        halt_cvt<<<(unsigned)((nW + 255)/256), 256>>>(Wi, (__nv_bfloat16*)pwh, (__nv_bfloat16*)pwl, nW);

        dim3 gg(NT/128, 12);
        halt_tcgemm<<<gg, 256, SMEM_TC>>>(K, bi, lens);

        halt_gru3<<<128, 256, SMEM_G3>>>(fxw, fB, Wh, bh, lens, (l == 4) ? 1 : 0);
    }
    halt_pool<<<256, 256>>>(fB, lens, Wc, bc, out);
}

// round 10
// speedup vs baseline: 4.5602x; 1.2218x over previous
#include <cuda_runtime.h>
#include <cuda_bf16.h>
#include <math.h>
#include <stdint.h>

#define Bn   256
#define Tn   512
#define NT   (Bn*Tn)          // 131072 tokens

// MMA GEMM smem: 4 tiles of [128][64] bf16 (SW128 swizzled) + bias
#define OFF_AH   0
#define OFF_AL   16384
#define OFF_BH   32768
#define OFF_BL   49152
#define OFF_BIAS 65536
#define SMEM_TC  (65536 + 512)

// GRU3 smem (bytes)
#define OFF_WH   0                    // Whh hi  [4 chunks][128 rows][64] bf16
#define OFF_WL   65536                // Whh lo
#define OFF_AH2  131072               // h hi    [4 chunks][32 rows][64] bf16
#define OFF_AL2  147456               // h lo
#define OFF_HOLD 163840               // fp32 [32][33]
#define OFF_PSM  168064               // fp32 [32][100]
#define SMEM_G3  180864

// ----------------- device scratch (bss-zeroed at module load) -----------------
__device__ float g_xw  [(size_t)NT*1536];   // input-gate precompute, reused per layer
__device__ float g_bufB[(size_t)NT*512];    // final-layer fp32 activations (pool input)
__device__ unsigned int g_h[2*2*256*256];   // h ping-pong, packed bf16 (hi | lo<<16)
__device__ int   g_perm[256];               // batch order sorted by length desc
__device__ __nv_bfloat16 g_ah[(size_t)NT*512];   // A hi split (GEMM input)
__device__ __nv_bfloat16 g_al[(size_t)NT*512];   // A lo split
__device__ __nv_bfloat16 g_wh[1536*512];         // W hi split
__device__ __nv_bfloat16 g_wl[1536*512];         // W lo split

// ----------------- mma.sync helpers (base ISA, compiles at compute_103) -----------------
__device__ __forceinline__ uint32_t smem_u32(const void* p) {
    uint32_t a;
    asm("{ .reg .u64 t; cvta.to.shared.u64 t, %1; cvt.u32.u64 %0, t; }" : "=r"(a) : "l"(p));
    return a;
}
#define SWIZ128(b) ((b) ^ (((b) >> 3) & 0x70))

__device__ __forceinline__ void ldsm4(uint32_t* r, uint32_t addr) {
    asm volatile("ldmatrix.sync.aligned.m8n8.x4.shared.b16 {%0,%1,%2,%3}, [%4];"
                 : "=r"(r[0]), "=r"(r[1]), "=r"(r[2]), "=r"(r[3]) : "r"(addr));
}
__device__ __forceinline__ void mma16816(float* c, const uint32_t* a, const uint32_t* b) {
    asm volatile("mma.sync.aligned.m16n8k16.row.col.f32.bf16.bf16.f32 "
                 "{%0,%1,%2,%3}, {%4,%5,%6,%7}, {%8,%9}, {%0,%1,%2,%3};"
                 : "+f"(c[0]), "+f"(c[1]), "+f"(c[2]), "+f"(c[3])
                 : "r"(a[0]), "r"(a[1]), "r"(a[2]), "r"(a[3]), "r"(b[0]), "r"(b[1]));
}

// fast gates: MUFU-based sigmoid/tanh (err ~1e-6, saturates correctly)
__device__ __forceinline__ float fsig(float x) {
    return __fdividef(1.f, 1.f + __expf(-x));
}
__device__ __forceinline__ float ftanh(float x) {
    return __fdividef(2.f, 1.f + __expf(-2.f*x)) - 1.f;
}

// ----------------- sort batch indices by length descending -----------------
__global__ void halt_sort_perm(const int* __restrict__ lengths) {
    __shared__ int key[256];
    __shared__ int idx[256];
    int tid = threadIdx.x;
    key[tid] = -lengths[tid];
    idx[tid] = tid;
    __syncthreads();
    for (int k = 2; k <= 256; k <<= 1)
        for (int j = k >> 1; j > 0; j >>= 1) {
            int ixj = tid ^ j;
            if (ixj > tid) {
                bool asc = ((tid & k) == 0);
                int a = key[tid], c = key[ixj];
                bool gt = a > c;
                if (asc == gt) {
                    key[tid] = c; key[ixj] = a;
                    int t2 = idx[tid]; idx[tid] = idx[ixj]; idx[ixj] = t2;
                }
            }
            __syncthreads();
        }
    g_perm[tid] = idx[tid];
}

// ----------------- input projection: LN -> Linear -> GELU -> Linear, writes bf16 hi/lo -----------------
__global__ void halt_proj(const float* __restrict__ x, const int* __restrict__ lengths,
                          const float* __restrict__ ln_g, const float* __restrict__ ln_b,
                          const float* __restrict__ w1, const float* __restrict__ b1,
                          const float* __restrict__ w2, const float* __restrict__ b2) {
    int token = blockIdx.x;
    int b = token >> 9, t = token & 511;
    if (t >= lengths[b]) return;
    __shared__ float sx[25], sn[25], sh1[128];
    int tid = threadIdx.x;
    if (tid < 25) sx[tid] = x[(size_t)token*25 + tid];
    __syncthreads();
    float mu = 0.f;
#pragma unroll
    for (int i = 0; i < 25; i++) mu += sx[i];
    mu *= (1.0f/25.0f);
    float var = 0.f;
#pragma unroll
    for (int i = 0; i < 25; i++) { float d = sx[i]-mu; var += d*d; }
    var *= (1.0f/25.0f);
    float rstd = rsqrtf(var + 1e-5f);
    if (tid < 25) sn[tid] = (sx[tid]-mu)*rstd*ln_g[tid] + ln_b[tid];
    __syncthreads();
    float a = b1[tid];
#pragma unroll
    for (int i = 0; i < 25; i++) a += sn[i]*w1[i*128 + tid];
    float ge = 0.5f*a*(1.0f + erff(a*0.70710678118654752440f));
    sh1[tid] = ge;
    __syncthreads();
    float o = b2[tid];
#pragma unroll 8
    for (int i = 0; i < 128; i++) o += sh1[i]*__ldg(&w2[i*128 + tid]);
    __nv_bfloat16 hbf = __float2bfloat16(o);
    g_ah[(size_t)token*128 + tid] = hbf;
    g_al[(size_t)token*128 + tid] = __float2bfloat16(o - __bfloat162float(hbf));
}

// ----------------- fp32 -> bf16 hi/lo split (weights only) -----------------
__global__ void halt_cvt(const float* __restrict__ src, __nv_bfloat16* __restrict__ hi,
                         __nv_bfloat16* __restrict__ lo, size_t n) {
    size_t i = (size_t)blockIdx.x*256 + threadIdx.x;
    if (i >= n) return;
    float v = src[i];
    __nv_bfloat16 h = __float2bfloat16(v);
    hi[i] = h;
    lo[i] = __float2bfloat16(v - __bfloat162float(h));
}

// ----------------- mma.sync GEMM: g_xw[M,1536] = A[M,K]*W[1536,K]^T + bias -----------------
__global__ __launch_bounds__(256)
void halt_tcgemm(int K, const float* __restrict__ bias, const int* __restrict__ lengths) {
    int m0 = blockIdx.x * 128;
    int n0 = blockIdx.y * 128;
    if ((m0 & 511) >= lengths[m0 >> 9]) return;   // fully-padded tile: outputs never read
    extern __shared__ char smem[];
    uint32_t sb = smem_u32(smem);
    int tid = threadIdx.x, warp = tid >> 5, lane = tid & 31;
    int wm = warp & 3, wn = warp >> 2;             // 4 x 2 warp grid, tile 32x64

    if (tid < 128) ((float*)(smem + OFF_BIAS))[tid] = bias[n0 + tid];

    const uint4* pAh = (const uint4*)g_ah;
    const uint4* pAl = (const uint4*)g_al;
    const uint4* pBh = (const uint4*)g_wh;
    const uint4* pBl = (const uint4*)g_wl;

    float acc[2][8][4];
#pragma unroll
    for (int mi = 0; mi < 2; mi++)
#pragma unroll
        for (int ni = 0; ni < 8; ni++)
#pragma unroll
            for (int q = 0; q < 4; q++) acc[mi][ni][q] = 0.f;

    int arow = wm*32 + (lane & 15);
    int acolsel = (lane >> 4) * 8;
    int brow = wn*64 + (lane & 7) + ((lane & 16) ? 8 : 0);
    int bcolsel = (lane & 8) ? 8 : 0;

    int nchunks = K >> 6;
    for (int c = 0; c < nchunks; c++) {
        int k0 = c << 6;
        for (int it = tid; it < 1024; it += 256) {
            int r = it >> 3, u = it & 7;
            uint32_t sw = SWIZ128((uint32_t)(r*128 + u*16));
            size_t ga = ((size_t)(m0 + r)*K + k0) / 8 + u;
            size_t gb = ((size_t)(n0 + r)*K + k0) / 8 + u;
            *(uint4*)(smem + OFF_AH + sw) = pAh[ga];
            *(uint4*)(smem + OFF_AL + sw) = pAl[ga];
            *(uint4*)(smem + OFF_BH + sw) = pBh[gb];
            *(uint4*)(smem + OFF_BL + sw) = pBl[gb];
        }
        __syncthreads();
#pragma unroll
        for (int ks = 0; ks < 4; ks++) {
            int kc = ks*16;
            uint32_t ah[2][4], al[2][4];
#pragma unroll
            for (int mi = 0; mi < 2; mi++) {
                uint32_t off = SWIZ128((uint32_t)((arow + mi*16)*128 + (kc + acolsel)*2));
                ldsm4(ah[mi], sb + OFF_AH + off);
                ldsm4(al[mi], sb + OFF_AL + off);
            }
            uint32_t bh[4][4], bl[4][4];
#pragma unroll
            for (int p = 0; p < 4; p++) {
                uint32_t off = SWIZ128((uint32_t)((brow + p*16)*128 + (kc + bcolsel)*2));
                ldsm4(bh[p], sb + OFF_BH + off);
                ldsm4(bl[p], sb + OFF_BL + off);
            }
#pragma unroll
            for (int mi = 0; mi < 2; mi++)
#pragma unroll
                for (int p = 0; p < 4; p++) {
                    mma16816(acc[mi][2*p],   ah[mi], &bh[p][0]);
                    mma16816(acc[mi][2*p],   ah[mi], &bl[p][0]);
                    mma16816(acc[mi][2*p],   al[mi], &bh[p][0]);
                    mma16816(acc[mi][2*p+1], ah[mi], &bh[p][2]);
                    mma16816(acc[mi][2*p+1], ah[mi], &bl[p][2]);
                    mma16816(acc[mi][2*p+1], al[mi], &bh[p][2]);
                }
        }
        __syncthreads();
    }

    const float* sbias = (const float*)(smem + OFF_BIAS);
#pragma unroll
    for (int mi = 0; mi < 2; mi++) {
        int rw = m0 + wm*32 + mi*16 + (lane >> 2);
#pragma unroll
        for (int ni = 0; ni < 8; ni++) {
            int cw = wn*64 + ni*8 + (lane & 3)*2;
            float bx = sbias[cw], by = sbias[cw + 1];
            float2 v0 = { acc[mi][ni][0] + bx, acc[mi][ni][1] + by };
            float2 v1 = { acc[mi][ni][2] + bx, acc[mi][ni][3] + by };
            *(float2*)&g_xw[(size_t)rw*1536 + n0 + cw]       = v0;
            *(float2*)&g_xw[(size_t)(rw + 8)*1536 + n0 + cw] = v1;
        }
    }
}

// ----------------- GRU v3b: HMMA recurrence, reg-cached B-hi, fast gates, packed h -----------------
// 128 blocks = 2 dir x 8 bt x 8 hc(32 j); cluster = 8 hc blocks of one (dir,bt).
__global__ __launch_bounds__(256, 1) __cluster_dims__(8, 1, 1)
void halt_gru3(const float* __restrict__ xw, float* __restrict__ y,
               const float* __restrict__ Whh, const float* __restrict__ bhh,
               const int* __restrict__ lengths, int last) {
    extern __shared__ char smg[];
    uint32_t sb = smem_u32(smg);
    float* holdp = (float*)(smg + OFF_HOLD);   // [32][33] persistent h_prev (own j-slice)
    float* psm   = (float*)(smg + OFF_PSM);    // [32][100]
    int grp = blockIdx.x >> 3;
    int hc  = blockIdx.x & 7;
    int dir = grp >> 3;
    int bt  = grp & 7;
    int j0  = hc * 32;
    int tid = threadIdx.x;
    int warp = tid >> 5, lane = tid & 31;
    int wm = warp >> 2, wn = warp & 3;         // 2 m-tiles x 4 n-groups(24 cols)
    int jj = tid & 31, squad = tid >> 5;

    // load Whh slice -> smem bf16 hi/lo, [4 chunks][128 rows pad][64], SW128
    const float* Wd = Whh + (size_t)dir*768*256;
    for (int idx = tid; idx < 96*256; idx += 256) {
        int r = idx >> 8, k = idx & 255;
        int g = r >> 5, jl = r & 31;
        float w = Wd[(size_t)(g*256 + j0 + jl)*256 + k];
        __nv_bfloat16 h = __float2bfloat16(w);
        __nv_bfloat16 l = __float2bfloat16(w - __bfloat162float(h));
        int chunk = k >> 6;
        uint32_t sw = SWIZ128((uint32_t)(r*128 + (k & 63)*2));
        *(__nv_bfloat16*)(smg + OFF_WH + chunk*16384 + sw) = h;
        *(__nv_bfloat16*)(smg + OFF_WL + chunk*16384 + sw) = l;
    }
    // init persistent hold (h0 = 0)
    for (int it = tid; it < 32*33; it += 256) holdp[it] = 0.f;
    float bh0 = bhh[dir*768 +       j0 + jj];
    float bh1 = bhh[dir*768 + 256 + j0 + jj];
    float bh2 = bhh[dir*768 + 512 + j0 + jj];
    int pb[4], lenv[4];
#pragma unroll
    for (int i = 0; i < 4; i++) {
        pb[i]   = g_perm[bt*32 + i*8 + squad];
        lenv[i] = lengths[pb[i]];
    }
    int tmax = lengths[g_perm[bt*32]];   // sorted desc -> tile max (same across cluster)
    __syncthreads();

    // cache static B-hi (weight) fragments in registers: 16 k16 x 6 used regs
    int n0w = wn * 24;
    int brow = n0w + (lane & 7) + ((lane & 16) ? 8 : 0);
    int bcolsel = (lane & 8) ? 8 : 0;
    uint32_t Bh[16][6];
#pragma unroll
    for (int k16 = 0; k16 < 16; k16++) {
        int chunk = k16 >> 2, kc = (k16 & 3)*16;
        uint32_t bsw0 = SWIZ128((uint32_t)(brow*128 + (kc + bcolsel)*2));
        uint32_t bsw1 = SWIZ128((uint32_t)((brow + 16)*128 + (kc + bcolsel)*2));
        uint32_t t0[4], t1[4];
        ldsm4(t0, sb + OFF_WH + chunk*16384 + bsw0);
        ldsm4(t1, sb + OFF_WH + chunk*16384 + bsw1);
        Bh[k16][0]=t0[0]; Bh[k16][1]=t0[1]; Bh[k16][2]=t0[2]; Bh[k16][3]=t0[3];
        Bh[k16][4]=t1[0]; Bh[k16][5]=t1[1];
    }

    int arow = wm*16 + (lane & 15);
    int acolsel = (lane >> 4) * 8;

    for (int t = 0; t < tmax; t++) {
        // prefetch xw gates for this thread's 4 elementwise samples (in flight thru phases 1-3)
        float xp0[4], xp1[4], xp2[4];
        int tok[4];
#pragma unroll
        for (int i = 0; i < 4; i++) {
            tok[i] = 0;
            if (t < lenv[i]) {
                tok[i] = dir ? (lenv[i] - 1 - t) : t;
                size_t base = (size_t)pb[i]*512 + tok[i];
                const float* xq = xw + base*1536 + dir*768 + j0 + jj;
                xp0[i] = __ldg(xq); xp1[i] = __ldg(xq + 256); xp2[i] = __ldg(xq + 512);
            }
        }
        // phase 1: load packed h (hi|lo<<16), byte_perm-unpack to A tiles
        const uint4* hin4 = (const uint4*)(g_h + ((size_t)((t & 1)*2 + dir)*256 + bt*32)*256);
        for (int it = tid; it < 2048; it += 256) {
            uint4 v = __ldcg(&hin4[it]);
            uint32_t hi01 = __byte_perm(v.x, v.y, 0x5410);
            uint32_t lo01 = __byte_perm(v.x, v.y, 0x7632);
            uint32_t hi23 = __byte_perm(v.z, v.w, 0x5410);
            uint32_t lo23 = __byte_perm(v.z, v.w, 0x7632);
            int s = it >> 6, q = it & 63;
            int chunk = q >> 4;
            uint32_t sw = SWIZ128((uint32_t)(s*128 + (q & 15)*8));
            *(uint2*)(smg + OFF_AH2 + chunk*4096 + sw) = make_uint2(hi01, hi23);
            *(uint2*)(smg + OFF_AL2 + chunk*4096 + sw) = make_uint2(lo01, lo23);
        }
        __syncthreads();

        // phase 2: mma — A ldsm + B-lo ldsm, B-hi from registers
        float acc[3][4];
#pragma unroll
        for (int q = 0; q < 3; q++) { acc[q][0]=0.f; acc[q][1]=0.f; acc[q][2]=0.f; acc[q][3]=0.f; }
#pragma unroll
        for (int k16 = 0; k16 < 16; k16++) {
            int chunk = k16 >> 2, kc = (k16 & 3)*16;
            uint32_t asw = SWIZ128((uint32_t)(arow*128 + (kc + acolsel)*2));
            uint32_t ah[4], al[4];
            ldsm4(ah, sb + OFF_AH2 + chunk*4096 + asw);
            ldsm4(al, sb + OFF_AL2 + chunk*4096 + asw);
            uint32_t bsw0 = SWIZ128((uint32_t)(brow*128 + (kc + bcolsel)*2));
            uint32_t bsw1 = SWIZ128((uint32_t)((brow + 16)*128 + (kc + bcolsel)*2));
            uint32_t bl01[4], bl2x[4];
            ldsm4(bl01, sb + OFF_WL + chunk*16384 + bsw0);
            ldsm4(bl2x, sb + OFF_WL + chunk*16384 + bsw1);
            mma16816(acc[0], ah, &Bh[k16][0]); mma16816(acc[0], ah, &bl01[0]); mma16816(acc[0], al, &Bh[k16][0]);
            mma16816(acc[1], ah, &Bh[k16][2]); mma16816(acc[1], ah, &bl01[2]); mma16816(acc[1], al, &Bh[k16][2]);
            mma16816(acc[2], ah, &Bh[k16][4]); mma16816(acc[2], ah, &bl2x[0]); mma16816(acc[2], al, &Bh[k16][4]);
        }

        // phase 3: dump fragments to psm[32][100]
        {
            int row = wm*16 + (lane >> 2);
#pragma unroll
            for (int q = 0; q < 3; q++) {
                int colb = n0w + q*8 + (lane & 3)*2;
                *(float2*)&psm[row*100 + colb]       = make_float2(acc[q][0], acc[q][1]);
                *(float2*)&psm[(row + 8)*100 + colb] = make_float2(acc[q][2], acc[q][3]);
            }
        }
        __syncthreads();

        // phase 4: fast gates; update holdp; write packed h-pong + next-layer A (or fp32 y)
#pragma unroll
        for (int i = 0; i < 4; i++) {
            if (t < lenv[i]) {
                int s = i*8 + squad;
                float gr = psm[s*100 +      jj] + bh0;
                float gz = psm[s*100 + 32 + jj] + bh1;
                float gn = psm[s*100 + 64 + jj] + bh2;
                float r = fsig(xp0[i] + gr);
                float z = fsig(xp1[i] + gz);
                float n = ftanh(xp2[i] + r*gn);
                float hold = holdp[s*33 + jj];
                float hnew = (1.f - z)*n + z*hold;
                holdp[s*33 + jj] = hnew;
                __nv_bfloat16 hb = __float2bfloat16(hnew);
                __nv_bfloat16 lb = __float2bfloat16(hnew - __bfloat162float(hb));
                size_t base = (size_t)pb[i]*512 + tok[i];
                size_t oc = base*512 + dir*256 + j0 + jj;
                if (last) {
                    y[oc] = hnew;
                } else {
                    g_ah[oc] = hb;
                    g_al[oc] = lb;
                }
                uint32_t packed = (uint32_t)__bfloat16_as_ushort(hb)
                                | ((uint32_t)__bfloat16_as_ushort(lb) << 16);
                g_h[((size_t)(((t+1) & 1)*2 + dir)*256 + bt*32 + s)*256 + j0 + jj] = packed;
            }
        }
        // cluster barrier: release our h stores, acquire peers'
        asm volatile("barrier.cluster.arrive.aligned;" ::: "memory");
        asm volatile("barrier.cluster.wait.aligned;"   ::: "memory");
    }
}

// ----------------- top-k pooling + classifier -----------------
__global__ __launch_bounds__(256)
void halt_pool(const float* __restrict__ H, const int* __restrict__ lengths,
               const float* __restrict__ Wc, const float* __restrict__ bc,
               float* __restrict__ out) {
    int b = blockIdx.x, tid = threadIdx.x;
    __shared__ float ns[512];
    __shared__ int   si[512];
    __shared__ float red[256];
    int len = lengths[b];
    int warp = tid >> 5, lane = tid & 31;
    for (int r = warp; r < 512; r += 8) {
        float sc = 1e9f;
        if (r < len) {
            const float* row = H + ((size_t)b*512 + r)*512;
            float acc = 0.f;
#pragma unroll 4
            for (int d = lane; d < 512; d += 32) { float v = row[d]; acc += v*v; }
#pragma unroll
            for (int o = 16; o > 0; o >>= 1) acc += __shfl_xor_sync(0xffffffffu, acc, o);
            sc = -sqrtf(acc);
        }
        if (lane == 0) { ns[r] = sc; si[r] = r; }
    }
    __syncthreads();
    for (int k = 2; k <= 512; k <<= 1)
        for (int j = k >> 1; j > 0; j >>= 1) {
            for (int i = tid; i < 512; i += 256) {
                int ixj = i ^ j;
                if (ixj > i) {
                    bool asc = ((i & k) == 0);
                    float a = ns[i], c = ns[ixj];
                    int ia = si[i], ic = si[ixj];
                    bool gt = (a > c) || (a == c && ia > ic);
                    if (asc == gt) { ns[i] = c; ns[ixj] = a; si[i] = ic; si[ixj] = ia; }
                }
            }
            __syncthreads();
        }
    int kk = (int)ceilf((float)len * 0.15f);
    if (kk < 1) kk = 1;
    float a0 = 0.f, a1 = 0.f;
    for (int i = 0; i < kk; i++) {
        int r = si[i];
        const float* row = H + ((size_t)b*512 + r)*512;
        a0 += row[tid]; a1 += row[tid + 256];
    }
    float kf = (float)kk;
    float part = (a0/kf)*Wc[tid] + (a1/kf)*Wc[tid + 256];
    red[tid] = part;
    __syncthreads();
    for (int s2 = 128; s2 > 0; s2 >>= 1) {
        if (tid < s2) red[tid] += red[tid + s2];
        __syncthreads();
    }
    if (tid == 0) out[b] = red[0] + bc[0];
}

// ----------------- host orchestration -----------------
extern "C" void kernel_launch(void* const* d_in, const int* in_sizes, int n_in,
                              void* d_out, int out_size) {
    const float* x    = (const float*)d_in[0];
    const int*   lens = (const int*)  d_in[1];
    const float* ln_g = (const float*)d_in[2];
    const float* ln_b = (const float*)d_in[3];
    const float* w1   = (const float*)d_in[4];
    const float* b1   = (const float*)d_in[5];
    const float* w2   = (const float*)d_in[6];
    const float* b2   = (const float*)d_in[7];
    const float* Wih0 = (const float*)d_in[8];
    const float* Whh0 = (const float*)d_in[9];
    const float* bih0 = (const float*)d_in[10];
    const float* bhh0 = (const float*)d_in[11];
    const float* Wih  = (const float*)d_in[12];
    const float* Whh  = (const float*)d_in[13];
    const float* bih  = (const float*)d_in[14];
    const float* bhh  = (const float*)d_in[15];
    const float* Wc   = (const float*)d_in[16];
    const float* bc   = (const float*)d_in[17];
    float* out = (float*)d_out;

    cudaFuncSetAttribute(halt_gru3, cudaFuncAttributeMaxDynamicSharedMemorySize, SMEM_G3);
    cudaFuncSetAttribute(halt_tcgemm, cudaFuncAttributeMaxDynamicSharedMemorySize, SMEM_TC);

    void *hp = 0, *pB = 0, *pxw = 0, *pwh = 0, *pwl = 0;
    cudaGetSymbolAddress(&hp,  g_h);
    cudaGetSymbolAddress(&pB,  g_bufB);
    cudaGetSymbolAddress(&pxw, g_xw);
    cudaGetSymbolAddress(&pwh, g_wh);
    cudaGetSymbolAddress(&pwl, g_wl);
    float* fB  = (float*)pB;
    float* fxw = (float*)pxw;

    halt_sort_perm<<<1, 256>>>(lens);
    halt_proj<<<NT, 128>>>(x, lens, ln_g, ln_b, w1, b1, w2, b2);

    for (int l = 0; l < 5; l++) {
        const float* Wi = l ? (Wih + (size_t)(l-1)*2*768*512) : Wih0;
        const float* bi = l ? (bih + (l-1)*1536) : bih0;
        const float* Wh = l ? (Whh + (size_t)(l-1)*2*768*256) : Whh0;
        const float* bh = l ? (bhh + (l-1)*1536) : bhh0;
        int K = l ? 512 : 128;
        cudaMemsetAsync(hp, 0, (size_t)2*2*256*256*sizeof(unsigned int));

        size_t nW = (size_t)1536 * K;
        halt_cvt<<<(unsigned)((nW + 255)/256), 256>>>(Wi, (__nv_bfloat16*)pwh, (__nv_bfloat16*)pwl, nW);

        dim3 gg(NT/128, 12);
        halt_tcgemm<<<gg, 256, SMEM_TC>>>(K, bi, lens);

        halt_gru3<<<128, 256, SMEM_G3>>>(fxw, fB, Wh, bh, lens, (l == 4) ? 1 : 0);
    }
    halt_pool<<<256, 256>>>(fB, lens, Wc, bc, out);
}

// round 11
// speedup vs baseline: 6.2981x; 1.3811x over previous
#include <cuda_runtime.h>
#include <cuda_bf16.h>
#include <math.h>
#include <stdint.h>

#define Bn   256
#define Tn   512
#define NT   (Bn*Tn)          // 131072 tokens

// tcgemm smem: 2 stages x 4 tiles of [128][64] bf16 (SW128) + bias
#define TCG_STAGE  65536
#define OFF_BIAS   131072
#define SMEM_TC    (131072 + 512)

// GRU3 smem (bytes)
#define OFF_WH   0                    // Whh hi  [4 chunks][128 rows][64] bf16
#define OFF_WL   65536                // Whh lo
#define OFF_AH2  131072               // h hi    [4 chunks][32 rows][64] bf16
#define OFF_AL2  147456               // h lo
#define OFF_HOLD 163840               // fp32 [32][33]
#define OFF_PSM  168064               // fp32 [32][100]
#define SMEM_G3  180864

// ----------------- device scratch (bss-zeroed at module load) -----------------
__device__ float g_xw  [(size_t)NT*1536];   // input-gate precompute, reused per layer
__device__ float g_bufB[(size_t)NT*512];    // final-layer fp32 activations (pool input)
__device__ int   g_perm[256];               // batch order sorted by length desc
__device__ __nv_bfloat16 g_ah[(size_t)NT*512];   // A hi split (GEMM input)
__device__ __nv_bfloat16 g_al[(size_t)NT*512];   // A lo split
__device__ __nv_bfloat16 g_wh[5*1536*512];       // W hi split, per-layer slots
__device__ __nv_bfloat16 g_wl[5*1536*512];       // W lo split
// h exchange in A-tile layout: [pp][dir][bt][chunk4][row32][col64] bf16
__device__ __nv_bfloat16 g_hxh[2*2*8*4*32*64];
__device__ __nv_bfloat16 g_hxl[2*2*8*4*32*64];

// ----------------- mma.sync helpers (base ISA, compiles at compute_103) -----------------
__device__ __forceinline__ uint32_t smem_u32(const void* p) {
    uint32_t a;
    asm("{ .reg .u64 t; cvta.to.shared.u64 t, %1; cvt.u32.u64 %0, t; }" : "=r"(a) : "l"(p));
    return a;
}
#define SWIZ128(b) ((b) ^ (((b) >> 3) & 0x70))

__device__ __forceinline__ void ldsm4(uint32_t* r, uint32_t addr) {
    asm volatile("ldmatrix.sync.aligned.m8n8.x4.shared.b16 {%0,%1,%2,%3}, [%4];"
                 : "=r"(r[0]), "=r"(r[1]), "=r"(r[2]), "=r"(r[3]) : "r"(addr));
}
__device__ __forceinline__ void mma16816(float* c, const uint32_t* a, const uint32_t* b) {
    asm volatile("mma.sync.aligned.m16n8k16.row.col.f32.bf16.bf16.f32 "
                 "{%0,%1,%2,%3}, {%4,%5,%6,%7}, {%8,%9}, {%0,%1,%2,%3};"
                 : "+f"(c[0]), "+f"(c[1]), "+f"(c[2]), "+f"(c[3])
                 : "r"(a[0]), "r"(a[1]), "r"(a[2]), "r"(a[3]), "r"(b[0]), "r"(b[1]));
}
__device__ __forceinline__ void cp16(uint32_t dst, const void* src) {
    asm volatile("cp.async.cg.shared.global [%0], [%1], 16;" :: "r"(dst), "l"(src) : "memory");
}

// fast gates: MUFU-based sigmoid/tanh (err ~1e-6, saturates correctly)
__device__ __forceinline__ float fsig(float x) {
    return __fdividef(1.f, 1.f + __expf(-x));
}
__device__ __forceinline__ float ftanh(float x) {
    return __fdividef(2.f, 1.f + __expf(-2.f*x)) - 1.f;
}

// ----------------- sort batch indices by length descending -----------------
__global__ void halt_sort_perm(const int* __restrict__ lengths) {
    __shared__ int key[256];
    __shared__ int idx[256];
    int tid = threadIdx.x;
    key[tid] = -lengths[tid];
    idx[tid] = tid;
    __syncthreads();
    for (int k = 2; k <= 256; k <<= 1)
        for (int j = k >> 1; j > 0; j >>= 1) {
            int ixj = tid ^ j;
            if (ixj > tid) {
                bool asc = ((tid & k) == 0);
                int a = key[tid], c = key[ixj];
                bool gt = a > c;
                if (asc == gt) {
                    key[tid] = c; key[ixj] = a;
                    int t2 = idx[tid]; idx[tid] = idx[ixj]; idx[ixj] = t2;
                }
            }
            __syncthreads();
        }
    g_perm[tid] = idx[tid];
}

// ----------------- input projection: LN -> Linear -> GELU -> Linear, writes bf16 hi/lo -----------------
__global__ void halt_proj(const float* __restrict__ x, const int* __restrict__ lengths,
                          const float* __restrict__ ln_g, const float* __restrict__ ln_b,
                          const float* __restrict__ w1, const float* __restrict__ b1,
                          const float* __restrict__ w2, const float* __restrict__ b2) {
    int token = blockIdx.x;
    int b = token >> 9, t = token & 511;
    if (t >= lengths[b]) return;
    __shared__ float sx[25], sn[25], sh1[128];
    int tid = threadIdx.x;
    if (tid < 25) sx[tid] = x[(size_t)token*25 + tid];
    __syncthreads();
    float mu = 0.f;
#pragma unroll
    for (int i = 0; i < 25; i++) mu += sx[i];
    mu *= (1.0f/25.0f);
    float var = 0.f;
#pragma unroll
    for (int i = 0; i < 25; i++) { float d = sx[i]-mu; var += d*d; }
    var *= (1.0f/25.0f);
    float rstd = rsqrtf(var + 1e-5f);
    if (tid < 25) sn[tid] = (sx[tid]-mu)*rstd*ln_g[tid] + ln_b[tid];
    __syncthreads();
    float a = b1[tid];
#pragma unroll
    for (int i = 0; i < 25; i++) a += sn[i]*w1[i*128 + tid];
    float ge = 0.5f*a*(1.0f + erff(a*0.70710678118654752440f));
    sh1[tid] = ge;
    __syncthreads();
    float o = b2[tid];
#pragma unroll 8
    for (int i = 0; i < 128; i++) o += sh1[i]*__ldg(&w2[i*128 + tid]);
    __nv_bfloat16 hbf = __float2bfloat16(o);
    g_ah[(size_t)token*128 + tid] = hbf;
    g_al[(size_t)token*128 + tid] = __float2bfloat16(o - __bfloat162float(hbf));
}

// ----------------- fp32 -> bf16 hi/lo split (weights; per-layer slots) -----------------
__global__ void halt_cvt(const float* __restrict__ src, __nv_bfloat16* __restrict__ hi,
                         __nv_bfloat16* __restrict__ lo, size_t n) {
    size_t i = (size_t)blockIdx.x*256 + threadIdx.x;
    if (i >= n) return;
    float v = src[i];
    __nv_bfloat16 h = __float2bfloat16(v);
    hi[i] = h;
    lo[i] = __float2bfloat16(v - __bfloat162float(h));
}

// ----------------- mma.sync GEMM with cp.async 2-stage pipeline -----------------
__global__ __launch_bounds__(256)
void halt_tcgemm(int K, const __nv_bfloat16* __restrict__ wh, const __nv_bfloat16* __restrict__ wl,
                 const float* __restrict__ bias, const int* __restrict__ lengths) {
    int m0 = blockIdx.x * 128;
    int n0 = blockIdx.y * 128;
    if ((m0 & 511) >= lengths[m0 >> 9]) return;   // fully-padded tile: outputs never read
    extern __shared__ char smem[];
    uint32_t sb = smem_u32(smem);
    int tid = threadIdx.x, warp = tid >> 5, lane = tid & 31;
    int wm = warp & 3, wn = warp >> 2;             // 4 x 2 warp grid, tile 32x64

    if (tid < 128) ((float*)(smem + OFF_BIAS))[tid] = bias[n0 + tid];

    const char* pAh = (const char*)g_ah;
    const char* pAl = (const char*)g_al;
    const char* pBh = (const char*)wh;
    const char* pBl = (const char*)wl;

    float acc[2][8][4];
#pragma unroll
    for (int mi = 0; mi < 2; mi++)
#pragma unroll
        for (int ni = 0; ni < 8; ni++)
#pragma unroll
            for (int q = 0; q < 4; q++) acc[mi][ni][q] = 0.f;

    int arow = wm*32 + (lane & 15);
    int acolsel = (lane >> 4) * 8;
    int brow = wn*64 + (lane & 7) + ((lane & 16) ? 8 : 0);
    int bcolsel = (lane & 8) ? 8 : 0;

    int nchunks = K >> 6;
    // stage chunk c into buffer buf
    auto stage = [&](int c, int buf) {
        uint32_t base = sb + buf*TCG_STAGE;
        for (int it = tid; it < 1024; it += 256) {
            int r = it >> 3, u = it & 7;
            uint32_t sw = SWIZ128((uint32_t)(r*128 + u*16));
            size_t ga = ((size_t)(m0 + r)*K + c*64)*2 + u*16;
            size_t gb = ((size_t)(n0 + r)*K + c*64)*2 + u*16;
            cp16(base + 0     + sw, pAh + ga);
            cp16(base + 16384 + sw, pAl + ga);
            cp16(base + 32768 + sw, pBh + gb);
            cp16(base + 49152 + sw, pBl + gb);
        }
        asm volatile("cp.async.commit_group;" ::: "memory");
    };

    stage(0, 0);
    for (int c = 0; c < nchunks; c++) {
        int buf = c & 1;
        if (c + 1 < nchunks) {
            stage(c + 1, buf ^ 1);
            asm volatile("cp.async.wait_group 1;" ::: "memory");
        } else {
            asm volatile("cp.async.wait_group 0;" ::: "memory");
        }
        __syncthreads();
        uint32_t base = sb + buf*TCG_STAGE;
#pragma unroll
        for (int ks = 0; ks < 4; ks++) {
            int kc = ks*16;
            uint32_t ah[2][4], al[2][4];
#pragma unroll
            for (int mi = 0; mi < 2; mi++) {
                uint32_t off = SWIZ128((uint32_t)((arow + mi*16)*128 + (kc + acolsel)*2));
                ldsm4(ah[mi], base + 0     + off);
                ldsm4(al[mi], base + 16384 + off);
            }
            uint32_t bh[4][4], bl[4][4];
#pragma unroll
            for (int p = 0; p < 4; p++) {
                uint32_t off = SWIZ128((uint32_t)((brow + p*16)*128 + (kc + bcolsel)*2));
                ldsm4(bh[p], base + 32768 + off);
                ldsm4(bl[p], base + 49152 + off);
            }
#pragma unroll
            for (int mi = 0; mi < 2; mi++)
#pragma unroll
                for (int p = 0; p < 4; p++) {
                    mma16816(acc[mi][2*p],   ah[mi], &bh[p][0]);
                    mma16816(acc[mi][2*p],   ah[mi], &bl[p][0]);
                    mma16816(acc[mi][2*p],   al[mi], &bh[p][0]);
                    mma16816(acc[mi][2*p+1], ah[mi], &bh[p][2]);
                    mma16816(acc[mi][2*p+1], ah[mi], &bl[p][2]);
                    mma16816(acc[mi][2*p+1], al[mi], &bh[p][2]);
                }
        }
        __syncthreads();
    }

    const float* sbias = (const float*)(smem + OFF_BIAS);
#pragma unroll
    for (int mi = 0; mi < 2; mi++) {
        int rw = m0 + wm*32 + mi*16 + (lane >> 2);
#pragma unroll
        for (int ni = 0; ni < 8; ni++) {
            int cw = wn*64 + ni*8 + (lane & 3)*2;
            float bx = sbias[cw], by = sbias[cw + 1];
            float2 v0 = { acc[mi][ni][0] + bx, acc[mi][ni][1] + by };
            float2 v1 = { acc[mi][ni][2] + bx, acc[mi][ni][3] + by };
            *(float2*)&g_xw[(size_t)rw*1536 + n0 + cw]       = v0;
            *(float2*)&g_xw[(size_t)(rw + 8)*1536 + n0 + cw] = v1;
        }
    }
}

// ----------------- GRU v4: direct-layout h exchange + step-ahead xw prefetch -----------------
// 128 blocks = 2 dir x 8 bt x 8 hc(32 j); cluster = 8 hc blocks of one (dir,bt).
__global__ __launch_bounds__(256, 1) __cluster_dims__(8, 1, 1)
void halt_gru3(const float* __restrict__ xw, float* __restrict__ y,
               const float* __restrict__ Whh, const float* __restrict__ bhh,
               const int* __restrict__ lengths, int last) {
    extern __shared__ char smg[];
    uint32_t sb = smem_u32(smg);
    float* holdp = (float*)(smg + OFF_HOLD);   // [32][33] persistent h_prev (own j-slice)
    float* psm   = (float*)(smg + OFF_PSM);    // [32][100]
    int grp = blockIdx.x >> 3;
    int hc  = blockIdx.x & 7;
    int dir = grp >> 3;
    int bt  = grp & 7;
    int j0  = hc * 32;
    int tid = threadIdx.x;
    int warp = tid >> 5, lane = tid & 31;
    int wm = warp >> 2, wn = warp & 3;         // 2 m-tiles x 4 n-groups(24 cols)
    int jj = tid & 31, squad = tid >> 5;

    // load Whh slice -> smem bf16 hi/lo, [4 chunks][128 rows pad][64], SW128
    const float* Wd = Whh + (size_t)dir*768*256;
    for (int idx = tid; idx < 96*256; idx += 256) {
        int r = idx >> 8, k = idx & 255;
        int g = r >> 5, jl = r & 31;
        float w = Wd[(size_t)(g*256 + j0 + jl)*256 + k];
        __nv_bfloat16 h = __float2bfloat16(w);
        __nv_bfloat16 l = __float2bfloat16(w - __bfloat162float(h));
        int chunk = k >> 6;
        uint32_t sw = SWIZ128((uint32_t)(r*128 + (k & 63)*2));
        *(__nv_bfloat16*)(smg + OFF_WH + chunk*16384 + sw) = h;
        *(__nv_bfloat16*)(smg + OFF_WL + chunk*16384 + sw) = l;
    }
    for (int it = tid; it < 32*33; it += 256) holdp[it] = 0.f;
    float bh0 = bhh[dir*768 +       j0 + jj];
    float bh1 = bhh[dir*768 + 256 + j0 + jj];
    float bh2 = bhh[dir*768 + 512 + j0 + jj];
    int pb[4], lenv[4];
#pragma unroll
    for (int i = 0; i < 4; i++) {
        pb[i]   = g_perm[bt*32 + i*8 + squad];
        lenv[i] = lengths[pb[i]];
    }
    int tmax = lengths[g_perm[bt*32]];   // sorted desc -> tile max (same across cluster)
    __syncthreads();

    // cache static B-hi (weight) fragments in registers: 16 k16 x 6 used regs
    int n0w = wn * 24;
    int brow = n0w + (lane & 7) + ((lane & 16) ? 8 : 0);
    int bcolsel = (lane & 8) ? 8 : 0;
    uint32_t Bh[16][6];
#pragma unroll
    for (int k16 = 0; k16 < 16; k16++) {
        int chunk = k16 >> 2, kc = (k16 & 3)*16;
        uint32_t bsw0 = SWIZ128((uint32_t)(brow*128 + (kc + bcolsel)*2));
        uint32_t bsw1 = SWIZ128((uint32_t)((brow + 16)*128 + (kc + bcolsel)*2));
        uint32_t t0[4], t1[4];
        ldsm4(t0, sb + OFF_WH + chunk*16384 + bsw0);
        ldsm4(t1, sb + OFF_WH + chunk*16384 + bsw1);
        Bh[k16][0]=t0[0]; Bh[k16][1]=t0[1]; Bh[k16][2]=t0[2]; Bh[k16][3]=t0[3];
        Bh[k16][4]=t1[0]; Bh[k16][5]=t1[1];
    }

    int arow = wm*16 + (lane & 15);
    int acolsel = (lane >> 4) * 8;
    int jcol = j0 + jj, jchunk = jcol >> 6, jc6 = jcol & 63;

    // xw prefetch helper (one step ahead)
    auto pref = [&](int tt, float* a0, float* a1, float* a2, int* tk) {
#pragma unroll
        for (int i = 0; i < 4; i++) {
            tk[i] = 0;
            if (tt < lenv[i]) {
                tk[i] = dir ? (lenv[i] - 1 - tt) : tt;
                size_t base = (size_t)pb[i]*512 + tk[i];
                const float* xq = xw + base*1536 + dir*768 + jcol;
                a0[i] = __ldg(xq); a1[i] = __ldg(xq + 256); a2[i] = __ldg(xq + 512);
            }
        }
    };
    float xp0[4], xp1[4], xp2[4];
    int tok[4];
    pref(0, xp0, xp1, xp2, tok);

    for (int t = 0; t < tmax; t++) {
        // phase 1: straight copy of peer-written A tiles (already swizzled layout)
        size_t tb = ((size_t)((t & 1)*2 + dir)*8 + bt) * 16384;
        const uint4* srch = (const uint4*)((const char*)g_hxh + tb);
        const uint4* srcl = (const uint4*)((const char*)g_hxl + tb);
#pragma unroll
        for (int q = 0; q < 4; q++) {
            int it = tid + q*256;
            uint4 vh = __ldcg(&srch[it]);
            uint4 vl = __ldcg(&srcl[it]);
            *(uint4*)(smg + OFF_AH2 + it*16) = vh;
            *(uint4*)(smg + OFF_AL2 + it*16) = vl;
        }
        __syncthreads();

        // phase 2: mma — A ldsm + B-lo ldsm, B-hi from registers
        float acc[3][4];
#pragma unroll
        for (int q = 0; q < 3; q++) { acc[q][0]=0.f; acc[q][1]=0.f; acc[q][2]=0.f; acc[q][3]=0.f; }
#pragma unroll
        for (int k16 = 0; k16 < 16; k16++) {
            int chunk = k16 >> 2, kc = (k16 & 3)*16;
            uint32_t asw = SWIZ128((uint32_t)(arow*128 + (kc + acolsel)*2));
            uint32_t ah[4], al[4];
            ldsm4(ah, sb + OFF_AH2 + chunk*4096 + asw);
            ldsm4(al, sb + OFF_AL2 + chunk*4096 + asw);
            uint32_t bsw0 = SWIZ128((uint32_t)(brow*128 + (kc + bcolsel)*2));
            uint32_t bsw1 = SWIZ128((uint32_t)((brow + 16)*128 + (kc + bcolsel)*2));
            uint32_t bl01[4], bl2x[4];
            ldsm4(bl01, sb + OFF_WL + chunk*16384 + bsw0);
            ldsm4(bl2x, sb + OFF_WL + chunk*16384 + bsw1);
            mma16816(acc[0], ah, &Bh[k16][0]); mma16816(acc[0], ah, &bl01[0]); mma16816(acc[0], al, &Bh[k16][0]);
            mma16816(acc[1], ah, &Bh[k16][2]); mma16816(acc[1], ah, &bl01[2]); mma16816(acc[1], al, &Bh[k16][2]);
            mma16816(acc[2], ah, &Bh[k16][4]); mma16816(acc[2], ah, &bl2x[0]); mma16816(acc[2], al, &Bh[k16][4]);
        }

        // phase 3: dump fragments to psm[32][100]
        {
            int row = wm*16 + (lane >> 2);
#pragma unroll
            for (int q = 0; q < 3; q++) {
                int colb = n0w + q*8 + (lane & 3)*2;
                *(float2*)&psm[row*100 + colb]       = make_float2(acc[q][0], acc[q][1]);
                *(float2*)&psm[(row + 8)*100 + colb] = make_float2(acc[q][2], acc[q][3]);
            }
        }
        // prefetch xw for NEXT step (lands during barrier + next phases 1-3)
        float nx0[4], nx1[4], nx2[4];
        int ntok[4];
        pref(t + 1, nx0, nx1, nx2, ntok);
        __syncthreads();

        // phase 4: fast gates; update holdp; write h directly in A-tile layout + next-layer A (or y)
        size_t tbn = ((size_t)(((t+1) & 1)*2 + dir)*8 + bt) * 16384;
#pragma unroll
        for (int i = 0; i < 4; i++) {
            if (t < lenv[i]) {
                int s = i*8 + squad;
                float gr = psm[s*100 +      jj] + bh0;
                float gz = psm[s*100 + 32 + jj] + bh1;
                float gn = psm[s*100 + 64 + jj] + bh2;
                float r = fsig(xp0[i] + gr);
                float z = fsig(xp1[i] + gz);
                float n = ftanh(xp2[i] + r*gn);
                float hold = holdp[s*33 + jj];
                float hnew = (1.f - z)*n + z*hold;
                holdp[s*33 + jj] = hnew;
                __nv_bfloat16 hb = __float2bfloat16(hnew);
                __nv_bfloat16 lb = __float2bfloat16(hnew - __bfloat162float(hb));
                size_t base = (size_t)pb[i]*512 + tok[i];
                size_t oc = base*512 + dir*256 + jcol;
                if (last) {
                    y[oc] = hnew;
                } else {
                    g_ah[oc] = hb;
                    g_al[oc] = lb;
                }
                uint32_t sw = SWIZ128((uint32_t)(s*128 + jc6*2));
                *(__nv_bfloat16*)((char*)g_hxh + tbn + jchunk*4096 + sw) = hb;
                *(__nv_bfloat16*)((char*)g_hxl + tbn + jchunk*4096 + sw) = lb;
            }
        }
        // cluster barrier: release our h stores, acquire peers'
        asm volatile("barrier.cluster.arrive.aligned;" ::: "memory");
        asm volatile("barrier.cluster.wait.aligned;"   ::: "memory");
#pragma unroll
        for (int i = 0; i < 4; i++) {
            xp0[i] = nx0[i]; xp1[i] = nx1[i]; xp2[i] = nx2[i]; tok[i] = ntok[i];
        }
    }
}

// ----------------- top-k pooling + classifier -----------------
__global__ __launch_bounds__(256)
void halt_pool(const float* __restrict__ H, const int* __restrict__ lengths,
               const float* __restrict__ Wc, const float* __restrict__ bc,
               float* __restrict__ out) {
    int b = blockIdx.x, tid = threadIdx.x;
    __shared__ float ns[512];
    __shared__ int   si[512];
    __shared__ float red[256];
    int len = lengths[b];
    int warp = tid >> 5, lane = tid & 31;
    for (int r = warp; r < 512; r += 8) {
        float sc = 1e9f;
        if (r < len) {
            const float* row = H + ((size_t)b*512 + r)*512;
            float acc = 0.f;
#pragma unroll 4
            for (int d = lane; d < 512; d += 32) { float v = row[d]; acc += v*v; }
#pragma unroll
            for (int o = 16; o > 0; o >>= 1) acc += __shfl_xor_sync(0xffffffffu, acc, o);
            sc = -sqrtf(acc);
        }
        if (lane == 0) { ns[r] = sc; si[r] = r; }
    }
    __syncthreads();
    for (int k = 2; k <= 512; k <<= 1)
        for (int j = k >> 1; j > 0; j >>= 1) {
            for (int i = tid; i < 512; i += 256) {
                int ixj = i ^ j;
                if (ixj > i) {
                    bool asc = ((i & k) == 0);
                    float a = ns[i], c = ns[ixj];
                    int ia = si[i], ic = si[ixj];
                    bool gt = (a > c) || (a == c && ia > ic);
                    if (asc == gt) { ns[i] = c; ns[ixj] = a; si[i] = ic; si[ixj] = ia; }
                }
            }
            __syncthreads();
        }
    int kk = (int)ceilf((float)len * 0.15f);
    if (kk < 1) kk = 1;
    float a0 = 0.f, a1 = 0.f;
    for (int i = 0; i < kk; i++) {
        int r = si[i];
        const float* row = H + ((size_t)b*512 + r)*512;
        a0 += row[tid]; a1 += row[tid + 256];
    }
    float kf = (float)kk;
    float part = (a0/kf)*Wc[tid] + (a1/kf)*Wc[tid + 256];
    red[tid] = part;
    __syncthreads();
    for (int s2 = 128; s2 > 0; s2 >>= 1) {
        if (tid < s2) red[tid] += red[tid + s2];
        __syncthreads();
    }
    if (tid == 0) out[b] = red[0] + bc[0];
}

// ----------------- host orchestration -----------------
extern "C" void kernel_launch(void* const* d_in, const int* in_sizes, int n_in,
                              void* d_out, int out_size) {
    const float* x    = (const float*)d_in[0];
    const int*   lens = (const int*)  d_in[1];
    const float* ln_g = (const float*)d_in[2];
    const float* ln_b = (const float*)d_in[3];
    const float* w1   = (const float*)d_in[4];
    const float* b1   = (const float*)d_in[5];
    const float* w2   = (const float*)d_in[6];
    const float* b2   = (const float*)d_in[7];
    const float* Wih0 = (const float*)d_in[8];
    const float* Whh0 = (const float*)d_in[9];
    const float* bih0 = (const float*)d_in[10];
    const float* bhh0 = (const float*)d_in[11];
    const float* Wih  = (const float*)d_in[12];
    const float* Whh  = (const float*)d_in[13];
    const float* bih  = (const float*)d_in[14];
    const float* bhh  = (const float*)d_in[15];
    const float* Wc   = (const float*)d_in[16];
    const float* bc   = (const float*)d_in[17];
    float* out = (float*)d_out;

    cudaFuncSetAttribute(halt_gru3, cudaFuncAttributeMaxDynamicSharedMemorySize, SMEM_G3);
    cudaFuncSetAttribute(halt_tcgemm, cudaFuncAttributeMaxDynamicSharedMemorySize, SMEM_TC);

    void *pB = 0, *pxw = 0, *pwh = 0, *pwl = 0, *phxh = 0, *phxl = 0;
    cudaGetSymbolAddress(&pB,   g_bufB);
    cudaGetSymbolAddress(&pxw,  g_xw);
    cudaGetSymbolAddress(&pwh,  g_wh);
    cudaGetSymbolAddress(&pwl,  g_wl);
    cudaGetSymbolAddress(&phxh, g_hxh);
    cudaGetSymbolAddress(&phxl, g_hxl);
    float* fB  = (float*)pB;
    float* fxw = (float*)pxw;

    halt_sort_perm<<<1, 256>>>(lens);
    halt_proj<<<NT, 128>>>(x, lens, ln_g, ln_b, w1, b1, w2, b2);

    // hoist all weight hi/lo splits (independent of layer order)
    for (int l = 0; l < 5; l++) {
        const float* Wi = l ? (Wih + (size_t)(l-1)*2*768*512) : Wih0;
        int K = l ? 512 : 128;
        size_t nW = (size_t)1536 * K;
        __nv_bfloat16* wh = (__nv_bfloat16*)pwh + (size_t)l*1536*512;
        __nv_bfloat16* wl = (__nv_bfloat16*)pwl + (size_t)l*1536*512;
        halt_cvt<<<(unsigned)((nW + 255)/256), 256>>>(Wi, wh, wl, nW);
    }

    for (int l = 0; l < 5; l++) {
        const float* bi = l ? (bih + (l-1)*1536) : bih0;
        const float* Wh = l ? (Whh + (size_t)(l-1)*2*768*256) : Whh0;
        const float* bh = l ? (bhh + (l-1)*1536) : bhh0;
        int K = l ? 512 : 128;
        const __nv_bfloat16* wh = (const __nv_bfloat16*)pwh + (size_t)l*1536*512;
        const __nv_bfloat16* wl = (const __nv_bfloat16*)pwl + (size_t)l*1536*512;

        cudaMemsetAsync(phxh, 0, (size_t)2*2*8*4*32*64*sizeof(__nv_bfloat16));
        cudaMemsetAsync(phxl, 0, (size_t)2*2*8*4*32*64*sizeof(__nv_bfloat16));

        dim3 gg(NT/128, 12);
        halt_tcgemm<<<gg, 256, SMEM_TC>>>(K, wh, wl, bi, lens);

        halt_gru3<<<128, 256, SMEM_G3>>>(fxw, fB, Wh, bh, lens, (l == 4) ? 1 : 0);
    }
    halt_pool<<<256, 256>>>(fB, lens, Wc, bc, out);
}